// round 1
// baseline (speedup 1.0000x reference)
#include <cuda_runtime.h>
#include <math.h>

#define NTOK  4096
#define CDIM  1024
#define HEADS 16
#define HD    64

// Scratch (allocation-guard-safe device globals)
__device__ float g_qkv[3 * HEADS * NTOK * HD];   // [which][h][n][d]
__device__ float g_attn[NTOK * CDIM];            // [n][h*64+d]

// ---------------------------------------------------------------------------
// Tiled fp32 GEMM: C[m,o] = sum_k A[m,k] * B[o,k]
// A: [M, CDIM] row-major, B: [Nout, CDIM] row-major (both K-contiguous)
// 64x64 tile, BK=16, 256 threads, 4x4 per thread.
// ---------------------------------------------------------------------------

__global__ __launch_bounds__(256) void qkv_gemm_kernel(const float* __restrict__ A,
                                                       const float* __restrict__ B) {
    __shared__ float As[16][64];
    __shared__ float Bs[16][64];
    const int tid = threadIdx.x;
    const int ty = tid >> 4, tx = tid & 15;
    const int bM = blockIdx.y * 64, bN = blockIdx.x * 64;
    const int lr = tid >> 2;           // 0..63
    const int lc = (tid & 3) << 2;     // 0,4,8,12
    const float* Aptr = A + (bM + lr) * CDIM + lc;
    const float* Bptr = B + (bN + lr) * CDIM + lc;
    float acc[4][4] = {};
    for (int kt = 0; kt < CDIM; kt += 16) {
        float4 av = *(const float4*)(Aptr + kt);
        float4 bv = *(const float4*)(Bptr + kt);
        As[lc + 0][lr] = av.x; As[lc + 1][lr] = av.y;
        As[lc + 2][lr] = av.z; As[lc + 3][lr] = av.w;
        Bs[lc + 0][lr] = bv.x; Bs[lc + 1][lr] = bv.y;
        Bs[lc + 2][lr] = bv.z; Bs[lc + 3][lr] = bv.w;
        __syncthreads();
        #pragma unroll
        for (int k = 0; k < 16; k++) {
            float4 a = *(const float4*)&As[k][ty << 2];
            float4 b = *(const float4*)&Bs[k][tx << 2];
            float ar[4] = {a.x, a.y, a.z, a.w};
            float br[4] = {b.x, b.y, b.z, b.w};
            #pragma unroll
            for (int i = 0; i < 4; i++)
                #pragma unroll
                for (int j = 0; j < 4; j++)
                    acc[i][j] = fmaf(ar[i], br[j], acc[i][j]);
        }
        __syncthreads();
    }
    // Scatter epilogue: o -> (which, h, d); write [which][h][n][d]
    #pragma unroll
    for (int i = 0; i < 4; i++) {
        int m = bM + (ty << 2) + i;
        #pragma unroll
        for (int j = 0; j < 4; j++) {
            int o = bN + (tx << 2) + j;
            int which = o >> 10;
            int h = (o >> 6) & 15;
            int d = o & 63;
            g_qkv[((which * HEADS + h) * NTOK + m) * HD + d] = acc[i][j];
        }
    }
}

__global__ __launch_bounds__(256) void proj_gemm_kernel(const float* __restrict__ B,
                                                        const float* __restrict__ bias,
                                                        float* __restrict__ out) {
    __shared__ float As[16][64];
    __shared__ float Bs[16][64];
    const int tid = threadIdx.x;
    const int ty = tid >> 4, tx = tid & 15;
    const int bM = blockIdx.y * 64, bN = blockIdx.x * 64;
    const int lr = tid >> 2;
    const int lc = (tid & 3) << 2;
    const float* Aptr = g_attn + (bM + lr) * CDIM + lc;
    const float* Bptr = B + (bN + lr) * CDIM + lc;
    float acc[4][4] = {};
    for (int kt = 0; kt < CDIM; kt += 16) {
        float4 av = *(const float4*)(Aptr + kt);
        float4 bv = *(const float4*)(Bptr + kt);
        As[lc + 0][lr] = av.x; As[lc + 1][lr] = av.y;
        As[lc + 2][lr] = av.z; As[lc + 3][lr] = av.w;
        Bs[lc + 0][lr] = bv.x; Bs[lc + 1][lr] = bv.y;
        Bs[lc + 2][lr] = bv.z; Bs[lc + 3][lr] = bv.w;
        __syncthreads();
        #pragma unroll
        for (int k = 0; k < 16; k++) {
            float4 a = *(const float4*)&As[k][ty << 2];
            float4 b = *(const float4*)&Bs[k][tx << 2];
            float ar[4] = {a.x, a.y, a.z, a.w};
            float br[4] = {b.x, b.y, b.z, b.w};
            #pragma unroll
            for (int i = 0; i < 4; i++)
                #pragma unroll
                for (int j = 0; j < 4; j++)
                    acc[i][j] = fmaf(ar[i], br[j], acc[i][j]);
        }
        __syncthreads();
    }
    #pragma unroll
    for (int i = 0; i < 4; i++) {
        int m = bM + (ty << 2) + i;
        #pragma unroll
        for (int j = 0; j < 4; j++) {
            int o = bN + (tx << 2) + j;
            out[m * CDIM + o] = acc[i][j] + bias[o];
        }
    }
}

// ---------------------------------------------------------------------------
// Causal flash attention, fp32. One block = 64 queries of one head.
// Smem: Q^T [d][r], K^T [d][j] (overlaid by P^T [j][r]), V [j][d] = 48 KB.
// Register micro-tiles 4x4; online softmax with 16-lane shfl reductions.
// ---------------------------------------------------------------------------

__global__ __launch_bounds__(256) void attn_kernel() {
    __shared__ float Qs[64][64];   // Q^T: [d][r]
    __shared__ float KP[64][64];   // K^T: [d][j], then P^T: [j][r]
    __shared__ float Vs[64][64];   // V:   [j][d]

    const int h  = blockIdx.y;
    const int qt = gridDim.x - 1 - blockIdx.x;   // heavy tiles first
    const int tid = threadIdx.x;
    const int ty = tid >> 4, tx = tid & 15;

    const float* Q = g_qkv + ((0 * HEADS + h) * NTOK + qt * 64) * HD;
    const float* K = g_qkv + ((1 * HEADS + h) * NTOK) * HD;
    const float* V = g_qkv + ((2 * HEADS + h) * NTOK) * HD;

    // load Q transposed
    {
        int r  = tid >> 2;
        int d0 = (tid & 3) << 4;   // 16 dims per thread
        const float* Qp = Q + r * HD + d0;
        #pragma unroll
        for (int u = 0; u < 16; u += 4) {
            float4 v = *(const float4*)(Qp + u);
            Qs[d0 + u + 0][r] = v.x; Qs[d0 + u + 1][r] = v.y;
            Qs[d0 + u + 2][r] = v.z; Qs[d0 + u + 3][r] = v.w;
        }
    }

    float o[4][4] = {};
    float mrow[4], lrow[4];
    #pragma unroll
    for (int i = 0; i < 4; i++) { mrow[i] = -INFINITY; lrow[i] = 0.f; }

    for (int kt = 0; kt <= qt; kt++) {
        __syncthreads();   // previous PV done with KP/Vs
        {
            int j  = tid >> 2;
            int d0 = (tid & 3) << 4;
            const float* Kp = K + (kt * 64 + j) * HD + d0;
            const float* Vp = V + (kt * 64 + j) * HD + d0;
            #pragma unroll
            for (int u = 0; u < 16; u += 4) {
                float4 kv = *(const float4*)(Kp + u);
                KP[d0 + u + 0][j] = kv.x; KP[d0 + u + 1][j] = kv.y;
                KP[d0 + u + 2][j] = kv.z; KP[d0 + u + 3][j] = kv.w;
                *(float4*)&Vs[j][d0 + u] = *(const float4*)(Vp + u);
            }
        }
        __syncthreads();

        // S = Q K^T  (k-dim = d)
        float s[4][4] = {};
        #pragma unroll 8
        for (int d = 0; d < 64; d++) {
            float4 a = *(const float4*)&Qs[d][ty << 2];
            float4 b = *(const float4*)&KP[d][tx << 2];
            float ar[4] = {a.x, a.y, a.z, a.w};
            float br[4] = {b.x, b.y, b.z, b.w};
            #pragma unroll
            for (int i = 0; i < 4; i++)
                #pragma unroll
                for (int j = 0; j < 4; j++)
                    s[i][j] = fmaf(ar[i], br[j], s[i][j]);
        }
        #pragma unroll
        for (int i = 0; i < 4; i++)
            #pragma unroll
            for (int j = 0; j < 4; j++)
                s[i][j] *= 0.125f;   // D^-0.5

        if (kt == qt) {   // causal mask inside diagonal tile
            #pragma unroll
            for (int i = 0; i < 4; i++)
                #pragma unroll
                for (int j = 0; j < 4; j++)
                    if (((tx << 2) + j) > ((ty << 2) + i)) s[i][j] = -INFINITY;
        }

        // online softmax
        #pragma unroll
        for (int i = 0; i < 4; i++) {
            float mx = fmaxf(fmaxf(s[i][0], s[i][1]), fmaxf(s[i][2], s[i][3]));
            #pragma unroll
            for (int off = 1; off < 16; off <<= 1)
                mx = fmaxf(mx, __shfl_xor_sync(0xffffffffu, mx, off));
            float mnew = fmaxf(mrow[i], mx);
            float scl  = __expf(mrow[i] - mnew);
            mrow[i] = mnew;
            float ls = 0.f;
            #pragma unroll
            for (int j = 0; j < 4; j++) {
                float p = __expf(s[i][j] - mnew);
                s[i][j] = p;
                ls += p;
            }
            #pragma unroll
            for (int off = 1; off < 16; off <<= 1)
                ls += __shfl_xor_sync(0xffffffffu, ls, off);
            lrow[i] = lrow[i] * scl + ls;
            #pragma unroll
            for (int j = 0; j < 4; j++) o[i][j] *= scl;
        }

        __syncthreads();   // everyone done reading K^T
        // store P^T into KP: [j][r]
        #pragma unroll
        for (int i = 0; i < 4; i++)
            #pragma unroll
            for (int j = 0; j < 4; j++)
                KP[(tx << 2) + j][(ty << 2) + i] = s[i][j];
        __syncthreads();

        // O += P V  (k-dim = j)
        #pragma unroll 8
        for (int j = 0; j < 64; j++) {
            float4 a = *(const float4*)&KP[j][ty << 2];
            float4 b = *(const float4*)&Vs[j][tx << 2];
            float ar[4] = {a.x, a.y, a.z, a.w};
            float br[4] = {b.x, b.y, b.z, b.w};
            #pragma unroll
            for (int i = 0; i < 4; i++)
                #pragma unroll
                for (int jj = 0; jj < 4; jj++)
                    o[i][jj] = fmaf(ar[i], br[jj], o[i][jj]);
        }
    }

    // normalize + write [n][h*64 + c]
    #pragma unroll
    for (int i = 0; i < 4; i++) {
        float inv = 1.f / lrow[i];
        int n = qt * 64 + (ty << 2) + i;
        float4 v;
        v.x = o[i][0] * inv; v.y = o[i][1] * inv;
        v.z = o[i][2] * inv; v.w = o[i][3] * inv;
        *(float4*)&g_attn[n * CDIM + h * HD + (tx << 2)] = v;
    }
}

// ---------------------------------------------------------------------------

extern "C" void kernel_launch(void* const* d_in, const int* in_sizes, int n_in,
                              void* d_out, int out_size) {
    const float* x      = (const float*)d_in[0];  // [4096, 1024]
    const float* w_qkv  = (const float*)d_in[1];  // [3072, 1024]
    const float* w_proj = (const float*)d_in[2];  // [1024, 1024]
    const float* b_proj = (const float*)d_in[3];  // [1024]
    float* out = (float*)d_out;                   // [4096, 1024]

    (void)in_sizes; (void)n_in; (void)out_size;

    dim3 g1(3 * CDIM / 64, NTOK / 64);   // 48 x 64
    qkv_gemm_kernel<<<g1, 256>>>(x, w_qkv);

    dim3 g2(NTOK / 64, HEADS);           // 64 x 16
    attn_kernel<<<g2, 256>>>();

    dim3 g3(CDIM / 64, NTOK / 64);       // 16 x 64
    proj_gemm_kernel<<<g3, 256>>>(w_proj, b_proj, out);
}

// round 9
// speedup vs baseline: 1.1829x; 1.1829x over previous
#include <cuda_runtime.h>
#include <math.h>
#include <stdint.h>
#include <mma.h>

using namespace nvcuda;

#define NTOK  4096
#define CDIM  1024
#define HEADS 16
#define HD    64

// Scratch (allocation-guard-safe device globals)
__device__ float g_qkv[3 * HEADS * NTOK * HD];   // [which][h][n][d]
__device__ float g_attn[NTOK * CDIM];            // [n][h*64+d]

// ---------------------------------------------------------------------------
// helpers
// ---------------------------------------------------------------------------
__device__ __forceinline__ float ftf32(float x) {   // round-to-nearest tf32
    uint32_t u;
    asm("cvt.rna.tf32.f32 %0, %1;" : "=r"(u) : "f"(x));
    return __uint_as_float(u);
}
__device__ __forceinline__ float4 f4tf32(float4 v) {
    v.x = ftf32(v.x); v.y = ftf32(v.y); v.z = ftf32(v.z); v.w = ftf32(v.w);
    return v;
}

// ---------------------------------------------------------------------------
// wmma tf32 GEMM: C[m,o] = sum_k A[m,k]*B[o,k]   (K = CDIM)
// 128x128 block tile, BK=32, 256 threads = 8 warps (2M x 4N), warp tile 64x32.
// wmma 16x16x8 tiles (4m x 2n per warp). Double-buffered smem.
// MODE 0: A = param, scatter to g_qkv.
// MODE 1: A = g_attn (device-resolved symbol! passing it from host gives the
//         host shadow address, which ATS silently dereferences), out + bias.
// ---------------------------------------------------------------------------
#define GPAD 36   // smem row stride (floats); 144 B = 9*16, float4-aligned

template <int MODE>
__global__ __launch_bounds__(256) void tc_gemm(const float* __restrict__ Ain,
                                               const float* __restrict__ B,
                                               const float* __restrict__ bias,
                                               float* __restrict__ out) {
    extern __shared__ float smem[];
    float* As = smem;                  // [2][128][GPAD]
    float* Bs = smem + 2 * 128 * GPAD; // [2][128][GPAD]

    const float* A = (MODE == 1) ? (const float*)g_attn : Ain;

    const int tid  = threadIdx.x;
    const int wid  = tid >> 5;
    const int lane = tid & 31;
    const int bN = blockIdx.x * 128;
    const int bM = blockIdx.y * 128;
    const int warp_m = (wid & 1) * 64;
    const int warp_n = (wid >> 1) * 32;
    const int NK = CDIM / 32;

    const int lr = tid >> 3;          // 0..31 (row block base)
    const int lc = (tid & 7) * 4;     // col within 32

    wmma::fragment<wmma::accumulator, 16, 16, 8, float> acc[4][2];
    #pragma unroll
    for (int mt = 0; mt < 4; mt++)
        #pragma unroll
        for (int nt = 0; nt < 2; nt++)
            wmma::fill_fragment(acc[mt][nt], 0.0f);

    // ---- prologue: tile 0 -> buffer 0 ----
    #pragma unroll
    for (int i = 0; i < 4; i++) {
        int r = lr + 32 * i;
        float4 av = f4tf32(*(const float4*)(A + (size_t)(bM + r) * CDIM + lc));
        float4 bv = f4tf32(*(const float4*)(B + (size_t)(bN + r) * CDIM + lc));
        *(float4*)(As + r * GPAD + lc) = av;
        *(float4*)(Bs + r * GPAD + lc) = bv;
    }
    __syncthreads();

    for (int kt = 0; kt < NK; kt++) {
        const int b = kt & 1;
        float4 pa[4], pb[4];
        if (kt + 1 < NK) {
            #pragma unroll
            for (int i = 0; i < 4; i++) {
                int r = lr + 32 * i;
                pa[i] = *(const float4*)(A + (size_t)(bM + r) * CDIM + (kt + 1) * 32 + lc);
                pb[i] = *(const float4*)(B + (size_t)(bN + r) * CDIM + (kt + 1) * 32 + lc);
            }
        }

        const float* Ab = As + b * 128 * GPAD;
        const float* Bb = Bs + b * 128 * GPAD;
        #pragma unroll
        for (int ks = 0; ks < 4; ks++) {
            const int k0 = ks * 8;
            wmma::fragment<wmma::matrix_a, 16, 16, 8, wmma::precision::tf32, wmma::row_major> af;
            wmma::fragment<wmma::matrix_b, 16, 16, 8, wmma::precision::tf32, wmma::col_major> bf[2];
            // B[o][k] row-major == (k,o) col-major with ld = GPAD
            #pragma unroll
            for (int nt = 0; nt < 2; nt++)
                wmma::load_matrix_sync(bf[nt], Bb + (warp_n + nt * 16) * GPAD + k0, GPAD);
            #pragma unroll
            for (int mt = 0; mt < 4; mt++) {
                wmma::load_matrix_sync(af, Ab + (warp_m + mt * 16) * GPAD + k0, GPAD);
                #pragma unroll
                for (int nt = 0; nt < 2; nt++)
                    wmma::mma_sync(acc[mt][nt], af, bf[nt], acc[mt][nt]);
            }
        }

        if (kt + 1 < NK) {
            const int nb = b ^ 1;
            #pragma unroll
            for (int i = 0; i < 4; i++) {
                int r = lr + 32 * i;
                *(float4*)(As + nb * 128 * GPAD + r * GPAD + lc) = f4tf32(pa[i]);
                *(float4*)(Bs + nb * 128 * GPAD + r * GPAD + lc) = f4tf32(pb[i]);
            }
        }
        __syncthreads();
    }

    // ---- epilogue: store_matrix_sync -> per-warp smem stage -> gmem ----
    float* stage = smem + wid * (16 * GPAD);   // 16 x GPAD floats per warp
    const int o_base = bN + warp_n;            // 32-col span, one (which,h)
    const int row = lane >> 1;
    const int c0  = (lane & 1) * 16;

    #pragma unroll
    for (int mt = 0; mt < 4; mt++) {
        __syncwarp();
        wmma::store_matrix_sync(stage,      acc[mt][0], GPAD, wmma::mem_row_major);
        wmma::store_matrix_sync(stage + 16, acc[mt][1], GPAD, wmma::mem_row_major);
        __syncwarp();

        const int m0 = bM + warp_m + mt * 16 + row;
        if (MODE == 0) {
            const int which = o_base >> 10;
            const int h = (o_base >> 6) & 15;
            const int d0 = (o_base & 63) + c0;
            float* dst = g_qkv + ((size_t)(which * HEADS + h) * NTOK + m0) * HD + d0;
            #pragma unroll
            for (int u = 0; u < 16; u += 4)
                *(float4*)(dst + u) = *(const float4*)(stage + row * GPAD + c0 + u);
        } else {
            float* dst = out + (size_t)m0 * CDIM + o_base + c0;
            #pragma unroll
            for (int u = 0; u < 16; u += 4) {
                float4 v = *(const float4*)(stage + row * GPAD + c0 + u);
                float4 bb = *(const float4*)(bias + o_base + c0 + u);
                v.x += bb.x; v.y += bb.y; v.z += bb.z; v.w += bb.w;
                *(float4*)(dst + u) = v;
            }
        }
    }
}

// ---------------------------------------------------------------------------
// Causal flash attention, fp32 SIMT — byte-identical to the round-1 version
// that passed at rel_err 7.5e-7.
// ---------------------------------------------------------------------------
__global__ __launch_bounds__(256) void attn_kernel() {
    __shared__ float Qs[64][64];   // Q^T: [d][r]
    __shared__ float KP[64][64];   // K^T: [d][j], then P^T: [j][r]
    __shared__ float Vs[64][64];   // V:   [j][d]

    const int h  = blockIdx.y;
    const int qt = gridDim.x - 1 - blockIdx.x;   // heavy tiles first
    const int tid = threadIdx.x;
    const int ty = tid >> 4, tx = tid & 15;

    const float* Q = g_qkv + ((0 * HEADS + h) * NTOK + qt * 64) * HD;
    const float* K = g_qkv + ((1 * HEADS + h) * NTOK) * HD;
    const float* V = g_qkv + ((2 * HEADS + h) * NTOK) * HD;

    {
        int r  = tid >> 2;
        int d0 = (tid & 3) << 4;
        const float* Qp = Q + r * HD + d0;
        #pragma unroll
        for (int u = 0; u < 16; u += 4) {
            float4 v = *(const float4*)(Qp + u);
            Qs[d0 + u + 0][r] = v.x; Qs[d0 + u + 1][r] = v.y;
            Qs[d0 + u + 2][r] = v.z; Qs[d0 + u + 3][r] = v.w;
        }
    }

    float o[4][4] = {};
    float mrow[4], lrow[4];
    #pragma unroll
    for (int i = 0; i < 4; i++) { mrow[i] = -INFINITY; lrow[i] = 0.f; }

    for (int kt = 0; kt <= qt; kt++) {
        __syncthreads();
        {
            int j  = tid >> 2;
            int d0 = (tid & 3) << 4;
            const float* Kp = K + (kt * 64 + j) * HD + d0;
            const float* Vp = V + (kt * 64 + j) * HD + d0;
            #pragma unroll
            for (int u = 0; u < 16; u += 4) {
                float4 kv = *(const float4*)(Kp + u);
                KP[d0 + u + 0][j] = kv.x; KP[d0 + u + 1][j] = kv.y;
                KP[d0 + u + 2][j] = kv.z; KP[d0 + u + 3][j] = kv.w;
                *(float4*)&Vs[j][d0 + u] = *(const float4*)(Vp + u);
            }
        }
        __syncthreads();

        float s[4][4] = {};
        #pragma unroll 8
        for (int d = 0; d < 64; d++) {
            float4 a = *(const float4*)&Qs[d][ty << 2];
            float4 b = *(const float4*)&KP[d][tx << 2];
            float ar[4] = {a.x, a.y, a.z, a.w};
            float br[4] = {b.x, b.y, b.z, b.w};
            #pragma unroll
            for (int i = 0; i < 4; i++)
                #pragma unroll
                for (int j = 0; j < 4; j++)
                    s[i][j] = fmaf(ar[i], br[j], s[i][j]);
        }
        #pragma unroll
        for (int i = 0; i < 4; i++)
            #pragma unroll
            for (int j = 0; j < 4; j++)
                s[i][j] *= 0.125f;

        if (kt == qt) {
            #pragma unroll
            for (int i = 0; i < 4; i++)
                #pragma unroll
                for (int j = 0; j < 4; j++)
                    if (((tx << 2) + j) > ((ty << 2) + i)) s[i][j] = -INFINITY;
        }

        #pragma unroll
        for (int i = 0; i < 4; i++) {
            float mx = fmaxf(fmaxf(s[i][0], s[i][1]), fmaxf(s[i][2], s[i][3]));
            #pragma unroll
            for (int off = 1; off < 16; off <<= 1)
                mx = fmaxf(mx, __shfl_xor_sync(0xffffffffu, mx, off));
            float mnew = fmaxf(mrow[i], mx);
            float scl  = __expf(mrow[i] - mnew);
            mrow[i] = mnew;
            float ls = 0.f;
            #pragma unroll
            for (int j = 0; j < 4; j++) {
                float p = __expf(s[i][j] - mnew);
                s[i][j] = p;
                ls += p;
            }
            #pragma unroll
            for (int off = 1; off < 16; off <<= 1)
                ls += __shfl_xor_sync(0xffffffffu, ls, off);
            lrow[i] = lrow[i] * scl + ls;
            #pragma unroll
            for (int j = 0; j < 4; j++) o[i][j] *= scl;
        }

        __syncthreads();
        #pragma unroll
        for (int i = 0; i < 4; i++)
            #pragma unroll
            for (int j = 0; j < 4; j++)
                KP[(tx << 2) + j][(ty << 2) + i] = s[i][j];
        __syncthreads();

        #pragma unroll 8
        for (int j = 0; j < 64; j++) {
            float4 a = *(const float4*)&KP[j][ty << 2];
            float4 b = *(const float4*)&Vs[j][tx << 2];
            float ar[4] = {a.x, a.y, a.z, a.w};
            float br[4] = {b.x, b.y, b.z, b.w};
            #pragma unroll
            for (int i = 0; i < 4; i++)
                #pragma unroll
                for (int jj = 0; jj < 4; jj++)
                    o[i][jj] = fmaf(ar[i], br[jj], o[i][jj]);
        }
    }

    #pragma unroll
    for (int i = 0; i < 4; i++) {
        float inv = 1.f / lrow[i];
        int n = qt * 64 + (ty << 2) + i;
        float4 v;
        v.x = o[i][0] * inv; v.y = o[i][1] * inv;
        v.z = o[i][2] * inv; v.w = o[i][3] * inv;
        *(float4*)&g_attn[n * CDIM + h * HD + (tx << 2)] = v;
    }
}

// ---------------------------------------------------------------------------

extern "C" void kernel_launch(void* const* d_in, const int* in_sizes, int n_in,
                              void* d_out, int out_size) {
    const float* x      = (const float*)d_in[0];  // [4096, 1024]
    const float* w_qkv  = (const float*)d_in[1];  // [3072, 1024]
    const float* w_proj = (const float*)d_in[2];  // [1024, 1024]
    const float* b_proj = (const float*)d_in[3];  // [1024]
    float* out = (float*)d_out;                   // [4096, 1024]

    (void)in_sizes; (void)n_in; (void)out_size;

    const int GEMM_SMEM = 4 * 128 * GPAD * 4;     // 73728 B
    cudaFuncSetAttribute(tc_gemm<0>, cudaFuncAttributeMaxDynamicSharedMemorySize, GEMM_SMEM);
    cudaFuncSetAttribute(tc_gemm<1>, cudaFuncAttributeMaxDynamicSharedMemorySize, GEMM_SMEM);

    dim3 g1(3 * CDIM / 128, NTOK / 128);   // 24 x 32
    tc_gemm<0><<<g1, 256, GEMM_SMEM>>>(x, w_qkv, nullptr, nullptr);

    dim3 g2(NTOK / 64, HEADS);             // 64 x 16
    attn_kernel<<<g2, 256>>>();

    dim3 g3(CDIM / 128, NTOK / 128);       // 8 x 32
    tc_gemm<1><<<g3, 256, GEMM_SMEM>>>(nullptr, w_proj, b_proj, out);
}

// round 10
// speedup vs baseline: 1.5793x; 1.3351x over previous
#include <cuda_runtime.h>
#include <math.h>
#include <stdint.h>
#include <mma.h>

using namespace nvcuda;

#define NTOK  4096
#define CDIM  1024
#define HEADS 16
#define HD    64

// Scratch (allocation-guard-safe device globals)
__device__ float g_qkv[3 * HEADS * NTOK * HD];   // [which][h][n][d]
__device__ float g_attn[NTOK * CDIM];            // [n][h*64+d]

// ---------------------------------------------------------------------------
// helpers
// ---------------------------------------------------------------------------
__device__ __forceinline__ float ftf32(float x) {   // round-to-nearest tf32
    uint32_t u;
    asm("cvt.rna.tf32.f32 %0, %1;" : "=r"(u) : "f"(x));
    return __uint_as_float(u);
}
__device__ __forceinline__ float4 f4tf32(float4 v) {
    v.x = ftf32(v.x); v.y = ftf32(v.y); v.z = ftf32(v.z); v.w = ftf32(v.w);
    return v;
}

// ---------------------------------------------------------------------------
// wmma tf32 GEMM (validated round 9): C[m,o] = sum_k A[m,k]*B[o,k]
// MODE 0: A = param, scatter to g_qkv. MODE 1: A = g_attn (device symbol!),
// out + bias.
// ---------------------------------------------------------------------------
#define GPAD 36

template <int MODE>
__global__ __launch_bounds__(256) void tc_gemm(const float* __restrict__ Ain,
                                               const float* __restrict__ B,
                                               const float* __restrict__ bias,
                                               float* __restrict__ out) {
    extern __shared__ float smem[];
    float* As = smem;                  // [2][128][GPAD]
    float* Bs = smem + 2 * 128 * GPAD; // [2][128][GPAD]

    const float* A = (MODE == 1) ? (const float*)g_attn : Ain;

    const int tid  = threadIdx.x;
    const int wid  = tid >> 5;
    const int lane = tid & 31;
    const int bN = blockIdx.x * 128;
    const int bM = blockIdx.y * 128;
    const int warp_m = (wid & 1) * 64;
    const int warp_n = (wid >> 1) * 32;
    const int NK = CDIM / 32;

    const int lr = tid >> 3;
    const int lc = (tid & 7) * 4;

    wmma::fragment<wmma::accumulator, 16, 16, 8, float> acc[4][2];
    #pragma unroll
    for (int mt = 0; mt < 4; mt++)
        #pragma unroll
        for (int nt = 0; nt < 2; nt++)
            wmma::fill_fragment(acc[mt][nt], 0.0f);

    #pragma unroll
    for (int i = 0; i < 4; i++) {
        int r = lr + 32 * i;
        float4 av = f4tf32(*(const float4*)(A + (size_t)(bM + r) * CDIM + lc));
        float4 bv = f4tf32(*(const float4*)(B + (size_t)(bN + r) * CDIM + lc));
        *(float4*)(As + r * GPAD + lc) = av;
        *(float4*)(Bs + r * GPAD + lc) = bv;
    }
    __syncthreads();

    for (int kt = 0; kt < NK; kt++) {
        const int b = kt & 1;
        float4 pa[4], pb[4];
        if (kt + 1 < NK) {
            #pragma unroll
            for (int i = 0; i < 4; i++) {
                int r = lr + 32 * i;
                pa[i] = *(const float4*)(A + (size_t)(bM + r) * CDIM + (kt + 1) * 32 + lc);
                pb[i] = *(const float4*)(B + (size_t)(bN + r) * CDIM + (kt + 1) * 32 + lc);
            }
        }

        const float* Ab = As + b * 128 * GPAD;
        const float* Bb = Bs + b * 128 * GPAD;
        #pragma unroll
        for (int ks = 0; ks < 4; ks++) {
            const int k0 = ks * 8;
            wmma::fragment<wmma::matrix_a, 16, 16, 8, wmma::precision::tf32, wmma::row_major> af;
            wmma::fragment<wmma::matrix_b, 16, 16, 8, wmma::precision::tf32, wmma::col_major> bf[2];
            #pragma unroll
            for (int nt = 0; nt < 2; nt++)
                wmma::load_matrix_sync(bf[nt], Bb + (warp_n + nt * 16) * GPAD + k0, GPAD);
            #pragma unroll
            for (int mt = 0; mt < 4; mt++) {
                wmma::load_matrix_sync(af, Ab + (warp_m + mt * 16) * GPAD + k0, GPAD);
                #pragma unroll
                for (int nt = 0; nt < 2; nt++)
                    wmma::mma_sync(acc[mt][nt], af, bf[nt], acc[mt][nt]);
            }
        }

        if (kt + 1 < NK) {
            const int nb = b ^ 1;
            #pragma unroll
            for (int i = 0; i < 4; i++) {
                int r = lr + 32 * i;
                *(float4*)(As + nb * 128 * GPAD + r * GPAD + lc) = f4tf32(pa[i]);
                *(float4*)(Bs + nb * 128 * GPAD + r * GPAD + lc) = f4tf32(pb[i]);
            }
        }
        __syncthreads();
    }

    float* stage = smem + wid * (16 * GPAD);
    const int o_base = bN + warp_n;
    const int row = lane >> 1;
    const int c0  = (lane & 1) * 16;

    #pragma unroll
    for (int mt = 0; mt < 4; mt++) {
        __syncwarp();
        wmma::store_matrix_sync(stage,      acc[mt][0], GPAD, wmma::mem_row_major);
        wmma::store_matrix_sync(stage + 16, acc[mt][1], GPAD, wmma::mem_row_major);
        __syncwarp();

        const int m0 = bM + warp_m + mt * 16 + row;
        if (MODE == 0) {
            const int which = o_base >> 10;
            const int h = (o_base >> 6) & 15;
            const int d0 = (o_base & 63) + c0;
            float* dst = g_qkv + ((size_t)(which * HEADS + h) * NTOK + m0) * HD + d0;
            #pragma unroll
            for (int u = 0; u < 16; u += 4)
                *(float4*)(dst + u) = *(const float4*)(stage + row * GPAD + c0 + u);
        } else {
            float* dst = out + (size_t)m0 * CDIM + o_base + c0;
            #pragma unroll
            for (int u = 0; u < 16; u += 4) {
                float4 v = *(const float4*)(stage + row * GPAD + c0 + u);
                float4 bb = *(const float4*)(bias + o_base + c0 + u);
                v.x += bb.x; v.y += bb.y; v.z += bb.z; v.w += bb.w;
                *(float4*)(dst + u) = v;
            }
        }
    }
}

// ---------------------------------------------------------------------------
// Causal flash attention on wmma tf32.
// Block = 256 threads (8 warps), one (head, 128-query tile). KV tiles of 64.
// Warp w owns query rows 16w..16w+15: S strip, softmax, P strip, PV, O rows —
// all warp-local; only the K/V tile load needs block-wide syncs.
// ---------------------------------------------------------------------------
#define FPAD 72

__global__ __launch_bounds__(256) void attn_mma() {
    extern __shared__ float sm[];
    float* Ks = sm;                   // [64][FPAD]   K tile, natural [j][d]
    float* Vs = Ks + 64 * FPAD;       // [64][FPAD]   V tile, natural [j][d]
    float* Ps = Vs + 64 * FPAD;       // [128][FPAD]  per-warp S/P/PV strips
    float* Os = Ps + 128 * FPAD;      // [128][FPAD]  O accum (Q staging first)

    const int h   = blockIdx.y;
    const int qt  = gridDim.x - 1 - blockIdx.x;   // heavy tiles first
    const int tid = threadIdx.x;
    const int wid = tid >> 5;

    const float* Q = g_qkv + ((size_t)(0 * HEADS + h) * NTOK + qt * 128) * HD;
    const float* K = g_qkv + ((size_t)(1 * HEADS + h) * NTOK) * HD;
    const float* V = g_qkv + ((size_t)(2 * HEADS + h) * NTOK) * HD;

    // ---- stage Q (tf32) into Os region, hoist fragments ----
    {
        int r = tid >> 1;
        int c = (tid & 1) * 32;
        #pragma unroll
        for (int u = 0; u < 32; u += 4)
            *(float4*)(Os + r * FPAD + c + u) =
                f4tf32(*(const float4*)(Q + (size_t)r * HD + c + u));
    }
    __syncthreads();

    wmma::fragment<wmma::matrix_a, 16, 16, 8, wmma::precision::tf32, wmma::row_major> qf[8];
    #pragma unroll
    for (int ks = 0; ks < 8; ks++)
        wmma::load_matrix_sync(qf[ks], Os + (wid * 16) * FPAD + ks * 8, FPAD);
    __syncthreads();

    // ---- zero O ----
    {
        int r = tid >> 1;
        int c = (tid & 1) * 32;
        #pragma unroll
        for (int u = 0; u < 32; u += 4)
            *(float4*)(Os + r * FPAD + c + u) = make_float4(0.f, 0.f, 0.f, 0.f);
    }

    const int row   = tid >> 1;          // owned query row (within tile)
    const int cbase = (tid & 1) * 32;    // owned 32-col span
    const int qg    = qt * 128 + row;    // global query index
    float mrow = -1e30f, lrow = 0.f;

    float* Pstrip = Ps + (wid * 16) * FPAD;
    float* Prow   = Ps + row * FPAD + cbase;

    const int nkt = 2 * qt + 2;
    for (int kt = 0; kt < nkt; kt++) {
        __syncthreads();   // all warps done with prev K/V
        {
            int r = tid >> 2;             // 0..63
            int c = (tid & 3) * 16;
            const float* Kp = K + (size_t)(kt * 64 + r) * HD + c;
            const float* Vp = V + (size_t)(kt * 64 + r) * HD + c;
            #pragma unroll
            for (int u = 0; u < 16; u += 4) {
                *(float4*)(Ks + r * FPAD + c + u) = f4tf32(*(const float4*)(Kp + u));
                *(float4*)(Vs + r * FPAD + c + u) = f4tf32(*(const float4*)(Vp + u));
            }
        }
        __syncthreads();

        // ---- S = Q K^T : warp strip [16][64] ----
        #pragma unroll
        for (int nt = 0; nt < 4; nt++) {
            wmma::fragment<wmma::accumulator, 16, 16, 8, float> acc;
            wmma::fill_fragment(acc, 0.f);
            #pragma unroll
            for (int ks = 0; ks < 8; ks++) {
                wmma::fragment<wmma::matrix_b, 16, 16, 8, wmma::precision::tf32, wmma::col_major> kf;
                wmma::load_matrix_sync(kf, Ks + (nt * 16) * FPAD + ks * 8, FPAD);
                wmma::mma_sync(acc, qf[ks], kf, acc);
            }
            wmma::store_matrix_sync(Pstrip + nt * 16, acc, FPAD, wmma::mem_row_major);
        }
        __syncwarp();

        // ---- online softmax on owned row span (2 threads/row) ----
        const int kgbase = kt * 64 + cbase;
        float mx = -1e30f;
        #pragma unroll
        for (int u = 0; u < 32; u++) {
            float v = Prow[u] * 0.125f;
            if (kgbase + u > qg) v = -1e30f;
            Prow[u] = v;
            mx = fmaxf(mx, v);
        }
        mx = fmaxf(mx, __shfl_xor_sync(0xffffffffu, mx, 1));
        float mnew = fmaxf(mrow, mx);
        float scl  = __expf(mrow - mnew);
        mrow = mnew;
        float ls = 0.f;
        #pragma unroll
        for (int u = 0; u < 32; u++) {
            float p = __expf(Prow[u] - mnew);
            ls += p;
            Prow[u] = ftf32(p);
        }
        ls += __shfl_xor_sync(0xffffffffu, ls, 1);
        lrow = lrow * scl + ls;
        __syncwarp();

        // ---- PV: A = own P strip (row-major), B = V natural row-major ----
        wmma::fragment<wmma::matrix_a, 16, 16, 8, wmma::precision::tf32, wmma::row_major> pf[8];
        #pragma unroll
        for (int ks = 0; ks < 8; ks++)
            wmma::load_matrix_sync(pf[ks], Pstrip + ks * 8, FPAD);
        #pragma unroll
        for (int nt = 0; nt < 4; nt++) {
            wmma::fragment<wmma::accumulator, 16, 16, 8, float> acc;
            wmma::fill_fragment(acc, 0.f);
            #pragma unroll
            for (int ks = 0; ks < 8; ks++) {
                wmma::fragment<wmma::matrix_b, 16, 16, 8, wmma::precision::tf32, wmma::row_major> vf;
                wmma::load_matrix_sync(vf, Vs + (ks * 8) * FPAD + nt * 16, FPAD);
                wmma::mma_sync(acc, pf[ks], vf, acc);
            }
            wmma::store_matrix_sync(Pstrip + nt * 16, acc, FPAD, wmma::mem_row_major);
        }
        __syncwarp();

        // ---- O update: own row span ----
        #pragma unroll
        for (int u = 0; u < 32; u += 4) {
            float4 ov = *(float4*)(Os + row * FPAD + cbase + u);
            float4 pv = *(const float4*)(Prow + u);
            ov.x = ov.x * scl + pv.x; ov.y = ov.y * scl + pv.y;
            ov.z = ov.z * scl + pv.z; ov.w = ov.w * scl + pv.w;
            *(float4*)(Os + row * FPAD + cbase + u) = ov;
        }
    }

    // ---- normalize + write ----
    float inv = 1.f / lrow;
    int n = qt * 128 + row;
    #pragma unroll
    for (int u = 0; u < 32; u += 4) {
        float4 ov = *(const float4*)(Os + row * FPAD + cbase + u);
        ov.x *= inv; ov.y *= inv; ov.z *= inv; ov.w *= inv;
        *(float4*)(g_attn + (size_t)n * CDIM + h * HD + cbase + u) = ov;
    }
}

// ---------------------------------------------------------------------------

extern "C" void kernel_launch(void* const* d_in, const int* in_sizes, int n_in,
                              void* d_out, int out_size) {
    const float* x      = (const float*)d_in[0];  // [4096, 1024]
    const float* w_qkv  = (const float*)d_in[1];  // [3072, 1024]
    const float* w_proj = (const float*)d_in[2];  // [1024, 1024]
    const float* b_proj = (const float*)d_in[3];  // [1024]
    float* out = (float*)d_out;                   // [4096, 1024]

    (void)in_sizes; (void)n_in; (void)out_size;

    const int GEMM_SMEM = 4 * 128 * GPAD * 4;          // 73728 B
    const int ATTN_SMEM = (64 + 64 + 128 + 128) * FPAD * 4;  // 110592 B
    cudaFuncSetAttribute(tc_gemm<0>, cudaFuncAttributeMaxDynamicSharedMemorySize, GEMM_SMEM);
    cudaFuncSetAttribute(tc_gemm<1>, cudaFuncAttributeMaxDynamicSharedMemorySize, GEMM_SMEM);
    cudaFuncSetAttribute(attn_mma,   cudaFuncAttributeMaxDynamicSharedMemorySize, ATTN_SMEM);

    dim3 g1(3 * CDIM / 128, NTOK / 128);   // 24 x 32
    tc_gemm<0><<<g1, 256, GEMM_SMEM>>>(x, w_qkv, nullptr, nullptr);

    dim3 g2(NTOK / 128, HEADS);            // 32 x 16
    attn_mma<<<g2, 256, ATTN_SMEM>>>();

    dim3 g3(CDIM / 128, NTOK / 128);       // 8 x 32
    tc_gemm<1><<<g3, 256, GEMM_SMEM>>>(nullptr, w_proj, b_proj, out);
}

// round 11
// speedup vs baseline: 1.9389x; 1.2277x over previous
#include <cuda_runtime.h>
#include <math.h>
#include <stdint.h>
#include <mma.h>

using namespace nvcuda;

#define NTOK  4096
#define CDIM  1024
#define HEADS 16
#define HD    64

// Scratch (allocation-guard-safe device globals)
__device__ float g_qkv[3 * HEADS * NTOK * HD];   // [which][h][n][d]
__device__ float g_attn[NTOK * CDIM];            // [n][h*64+d]

// ---------------------------------------------------------------------------
// helpers
// ---------------------------------------------------------------------------
__device__ __forceinline__ float ftf32(float x) {   // round-to-nearest tf32
    uint32_t u;
    asm("cvt.rna.tf32.f32 %0, %1;" : "=r"(u) : "f"(x));
    return __uint_as_float(u);
}
__device__ __forceinline__ float4 f4tf32(float4 v) {
    v.x = ftf32(v.x); v.y = ftf32(v.y); v.z = ftf32(v.z); v.w = ftf32(v.w);
    return v;
}

// mma.sync m16n8k8 tf32: D = A*B + C   (A row-major 16x8, B col-major 8x8)
__device__ __forceinline__ void mma8(float* d, const uint32_t* a,
                                     const uint32_t* b, const float* c) {
    asm volatile(
        "mma.sync.aligned.m16n8k8.row.col.f32.tf32.tf32.f32 "
        "{%0,%1,%2,%3}, {%4,%5,%6,%7}, {%8,%9}, {%10,%11,%12,%13};"
        : "=f"(d[0]), "=f"(d[1]), "=f"(d[2]), "=f"(d[3])
        : "r"(a[0]), "r"(a[1]), "r"(a[2]), "r"(a[3]),
          "r"(b[0]), "r"(b[1]),
          "f"(c[0]), "f"(c[1]), "f"(c[2]), "f"(c[3]));
}

// ---------------------------------------------------------------------------
// wmma tf32 GEMM (validated round 9/10): C[m,o] = sum_k A[m,k]*B[o,k]
// MODE 0: A = param, scatter to g_qkv. MODE 1: A = g_attn (device symbol!),
// out + bias.
// ---------------------------------------------------------------------------
#define GPAD 36

template <int MODE>
__global__ __launch_bounds__(256) void tc_gemm(const float* __restrict__ Ain,
                                               const float* __restrict__ B,
                                               const float* __restrict__ bias,
                                               float* __restrict__ out) {
    extern __shared__ float smem[];
    float* As = smem;                  // [2][128][GPAD]
    float* Bs = smem + 2 * 128 * GPAD; // [2][128][GPAD]

    const float* A = (MODE == 1) ? (const float*)g_attn : Ain;

    const int tid  = threadIdx.x;
    const int wid  = tid >> 5;
    const int lane = tid & 31;
    const int bN = blockIdx.x * 128;
    const int bM = blockIdx.y * 128;
    const int warp_m = (wid & 1) * 64;
    const int warp_n = (wid >> 1) * 32;
    const int NK = CDIM / 32;

    const int lr = tid >> 3;
    const int lc = (tid & 7) * 4;

    wmma::fragment<wmma::accumulator, 16, 16, 8, float> acc[4][2];
    #pragma unroll
    for (int mt = 0; mt < 4; mt++)
        #pragma unroll
        for (int nt = 0; nt < 2; nt++)
            wmma::fill_fragment(acc[mt][nt], 0.0f);

    #pragma unroll
    for (int i = 0; i < 4; i++) {
        int r = lr + 32 * i;
        float4 av = f4tf32(*(const float4*)(A + (size_t)(bM + r) * CDIM + lc));
        float4 bv = f4tf32(*(const float4*)(B + (size_t)(bN + r) * CDIM + lc));
        *(float4*)(As + r * GPAD + lc) = av;
        *(float4*)(Bs + r * GPAD + lc) = bv;
    }
    __syncthreads();

    for (int kt = 0; kt < NK; kt++) {
        const int b = kt & 1;
        float4 pa[4], pb[4];
        if (kt + 1 < NK) {
            #pragma unroll
            for (int i = 0; i < 4; i++) {
                int r = lr + 32 * i;
                pa[i] = *(const float4*)(A + (size_t)(bM + r) * CDIM + (kt + 1) * 32 + lc);
                pb[i] = *(const float4*)(B + (size_t)(bN + r) * CDIM + (kt + 1) * 32 + lc);
            }
        }

        const float* Ab = As + b * 128 * GPAD;
        const float* Bb = Bs + b * 128 * GPAD;
        #pragma unroll
        for (int ks = 0; ks < 4; ks++) {
            const int k0 = ks * 8;
            wmma::fragment<wmma::matrix_a, 16, 16, 8, wmma::precision::tf32, wmma::row_major> af;
            wmma::fragment<wmma::matrix_b, 16, 16, 8, wmma::precision::tf32, wmma::col_major> bf[2];
            #pragma unroll
            for (int nt = 0; nt < 2; nt++)
                wmma::load_matrix_sync(bf[nt], Bb + (warp_n + nt * 16) * GPAD + k0, GPAD);
            #pragma unroll
            for (int mt = 0; mt < 4; mt++) {
                wmma::load_matrix_sync(af, Ab + (warp_m + mt * 16) * GPAD + k0, GPAD);
                #pragma unroll
                for (int nt = 0; nt < 2; nt++)
                    wmma::mma_sync(acc[mt][nt], af, bf[nt], acc[mt][nt]);
            }
        }

        if (kt + 1 < NK) {
            const int nb = b ^ 1;
            #pragma unroll
            for (int i = 0; i < 4; i++) {
                int r = lr + 32 * i;
                *(float4*)(As + nb * 128 * GPAD + r * GPAD + lc) = f4tf32(pa[i]);
                *(float4*)(Bs + nb * 128 * GPAD + r * GPAD + lc) = f4tf32(pb[i]);
            }
        }
        __syncthreads();
    }

    float* stage = smem + wid * (16 * GPAD);
    const int o_base = bN + warp_n;
    const int row = lane >> 1;
    const int c0  = (lane & 1) * 16;

    #pragma unroll
    for (int mt = 0; mt < 4; mt++) {
        __syncwarp();
        wmma::store_matrix_sync(stage,      acc[mt][0], GPAD, wmma::mem_row_major);
        wmma::store_matrix_sync(stage + 16, acc[mt][1], GPAD, wmma::mem_row_major);
        __syncwarp();

        const int m0 = bM + warp_m + mt * 16 + row;
        if (MODE == 0) {
            const int which = o_base >> 10;
            const int h = (o_base >> 6) & 15;
            const int d0 = (o_base & 63) + c0;
            float* dst = g_qkv + ((size_t)(which * HEADS + h) * NTOK + m0) * HD + d0;
            #pragma unroll
            for (int u = 0; u < 16; u += 4)
                *(float4*)(dst + u) = *(const float4*)(stage + row * GPAD + c0 + u);
        } else {
            float* dst = out + (size_t)m0 * CDIM + o_base + c0;
            #pragma unroll
            for (int u = 0; u < 16; u += 4) {
                float4 v = *(const float4*)(stage + row * GPAD + c0 + u);
                float4 bb = *(const float4*)(bias + o_base + c0 + u);
                v.x += bb.x; v.y += bb.y; v.z += bb.z; v.w += bb.w;
                *(float4*)(dst + u) = v;
            }
        }
    }
}

// ---------------------------------------------------------------------------
// Causal flash attention, register-resident raw mma.sync m16n8k8 tf32.
// Block = 128 threads (4 warps), one (head, 64-query tile).
// Warp w owns rows 16w..16w+15. S/softmax/O live in registers; smem only for
// K/V tiles and the P (C-layout -> A-layout) staging strip.
// ---------------------------------------------------------------------------
#define APAD 72   // smem row stride (floats)

__global__ __launch_bounds__(128) void attn_kernel() {
    extern __shared__ float smA[];
    float* Ks = smA;                  // [64][APAD]  K tile, natural [j][d]
    float* Vs = smA + 64 * APAD;      // [64][APAD]  V tile, natural [j][d]
    float* Ps = smA + 2 * 64 * APAD;  // [64][APAD]  Q staging, then P

    const int h  = blockIdx.y;
    const int qt = gridDim.x - 1 - blockIdx.x;   // heavy tiles first
    const int tid  = threadIdx.x;
    const int wid  = tid >> 5;
    const int lane = tid & 31;
    const int g    = lane >> 2;       // group row 0..7
    const int t4   = lane & 3;        // 0..3

    const float* Q = g_qkv + ((size_t)(0 * HEADS + h) * NTOK + qt * 64) * HD;
    const float* K = g_qkv + ((size_t)(1 * HEADS + h) * NTOK) * HD;
    const float* V = g_qkv + ((size_t)(2 * HEADS + h) * NTOK) * HD;

    // ---- stage Q into Ps (tf32), then hoist fragments ----
    {
        int r = tid >> 1;
        int c0 = (tid & 1) * 32;
        #pragma unroll
        for (int u = 0; u < 32; u += 4)
            *(float4*)(Ps + r * APAD + c0 + u) =
                f4tf32(*(const float4*)(Q + (size_t)r * HD + c0 + u));
    }
    __syncthreads();

    uint32_t qf[8][4];
    {
        int r = wid * 16 + g;
        #pragma unroll
        for (int ks = 0; ks < 8; ks++) {
            int k0 = ks * 8 + t4;
            qf[ks][0] = __float_as_uint(Ps[r * APAD + k0]);
            qf[ks][1] = __float_as_uint(Ps[(r + 8) * APAD + k0]);
            qf[ks][2] = __float_as_uint(Ps[r * APAD + k0 + 4]);
            qf[ks][3] = __float_as_uint(Ps[(r + 8) * APAD + k0 + 4]);
        }
    }
    __syncthreads();

    float o[8][4] = {};
    float mA = -1e30f, mB = -1e30f, lA = 0.f, lB = 0.f;

    const int rqA = wid * 16 + g;     // local row (c0/c1)
    const int rqB = rqA + 8;          // local row (c2/c3)

    for (int kt = 0; kt <= qt; kt++) {
        __syncthreads();   // previous iteration done with Ks/Vs/Ps
        {
            int r = tid >> 1;
            int c0 = (tid & 1) * 32;
            const float* Kp = K + (size_t)(kt * 64 + r) * HD + c0;
            const float* Vp = V + (size_t)(kt * 64 + r) * HD + c0;
            #pragma unroll
            for (int u = 0; u < 32; u += 4) {
                *(float4*)(Ks + r * APAD + c0 + u) = f4tf32(*(const float4*)(Kp + u));
                *(float4*)(Vs + r * APAD + c0 + u) = f4tf32(*(const float4*)(Vp + u));
            }
        }
        __syncthreads();

        // ---- S = Q K^T ----
        float s[8][4] = {};
        #pragma unroll
        for (int ks = 0; ks < 8; ks++) {
            int k0 = ks * 8 + t4;
            #pragma unroll
            for (int nt = 0; nt < 8; nt++) {
                uint32_t bf[2];
                int j = nt * 8 + g;
                bf[0] = __float_as_uint(Ks[j * APAD + k0]);
                bf[1] = __float_as_uint(Ks[j * APAD + k0 + 4]);
                mma8(s[nt], qf[ks], bf, s[nt]);
            }
        }

        // scale + causal mask (diagonal tile only; local idx valid, 64-aligned)
        #pragma unroll
        for (int nt = 0; nt < 8; nt++) {
            #pragma unroll
            for (int c = 0; c < 4; c++) s[nt][c] *= 0.125f;
            if (kt == qt) {
                int j0 = nt * 8 + 2 * t4;
                if (j0 > rqA)     s[nt][0] = -1e30f;
                if (j0 + 1 > rqA) s[nt][1] = -1e30f;
                if (j0 > rqB)     s[nt][2] = -1e30f;
                if (j0 + 1 > rqB) s[nt][3] = -1e30f;
            }
        }

        // ---- online softmax (rows rqA, rqB; reduce over t4 lanes) ----
        float mxA = -1e30f, mxB = -1e30f;
        #pragma unroll
        for (int nt = 0; nt < 8; nt++) {
            mxA = fmaxf(mxA, fmaxf(s[nt][0], s[nt][1]));
            mxB = fmaxf(mxB, fmaxf(s[nt][2], s[nt][3]));
        }
        #pragma unroll
        for (int off = 1; off < 4; off <<= 1) {
            mxA = fmaxf(mxA, __shfl_xor_sync(0xffffffffu, mxA, off));
            mxB = fmaxf(mxB, __shfl_xor_sync(0xffffffffu, mxB, off));
        }
        float mnA = fmaxf(mA, mxA), mnB = fmaxf(mB, mxB);
        float sclA = __expf(mA - mnA), sclB = __expf(mB - mnB);
        mA = mnA; mB = mnB;

        float lsA = 0.f, lsB = 0.f;
        #pragma unroll
        for (int nt = 0; nt < 8; nt++) {
            float p0 = __expf(s[nt][0] - mnA);
            float p1 = __expf(s[nt][1] - mnA);
            float p2 = __expf(s[nt][2] - mnB);
            float p3 = __expf(s[nt][3] - mnB);
            lsA += p0 + p1; lsB += p2 + p3;
            int j0 = nt * 8 + 2 * t4;
            Ps[rqA * APAD + j0]     = ftf32(p0);
            Ps[rqA * APAD + j0 + 1] = ftf32(p1);
            Ps[rqB * APAD + j0]     = ftf32(p2);
            Ps[rqB * APAD + j0 + 1] = ftf32(p3);
        }
        #pragma unroll
        for (int off = 1; off < 4; off <<= 1) {
            lsA += __shfl_xor_sync(0xffffffffu, lsA, off);
            lsB += __shfl_xor_sync(0xffffffffu, lsB, off);
        }
        lA = lA * sclA + lsA;
        lB = lB * sclB + lsB;
        #pragma unroll
        for (int nt = 0; nt < 8; nt++) {
            o[nt][0] *= sclA; o[nt][1] *= sclA;
            o[nt][2] *= sclB; o[nt][3] *= sclB;
        }
        __syncwarp();   // P strip (warp-local rows) visible to warp

        // ---- O += P V ----
        #pragma unroll
        for (int ks = 0; ks < 8; ks++) {
            int k0 = ks * 8 + t4;
            uint32_t pf[4];
            pf[0] = __float_as_uint(Ps[rqA * APAD + k0]);
            pf[1] = __float_as_uint(Ps[rqB * APAD + k0]);
            pf[2] = __float_as_uint(Ps[rqA * APAD + k0 + 4]);
            pf[3] = __float_as_uint(Ps[rqB * APAD + k0 + 4]);
            #pragma unroll
            for (int nt = 0; nt < 8; nt++) {
                uint32_t vf[2];
                int d = nt * 8 + g;
                vf[0] = __float_as_uint(Vs[k0 * APAD + d]);
                vf[1] = __float_as_uint(Vs[(k0 + 4) * APAD + d]);
                mma8(o[nt], pf, vf, o[nt]);
            }
        }
    }

    // ---- normalize + write ----
    float invA = 1.f / lA, invB = 1.f / lB;
    int nA = qt * 64 + rqA, nB = qt * 64 + rqB;
    #pragma unroll
    for (int nt = 0; nt < 8; nt++) {
        int c = h * HD + nt * 8 + 2 * t4;
        *(float2*)(g_attn + (size_t)nA * CDIM + c) =
            make_float2(o[nt][0] * invA, o[nt][1] * invA);
        *(float2*)(g_attn + (size_t)nB * CDIM + c) =
            make_float2(o[nt][2] * invB, o[nt][3] * invB);
    }
}

// ---------------------------------------------------------------------------

extern "C" void kernel_launch(void* const* d_in, const int* in_sizes, int n_in,
                              void* d_out, int out_size) {
    const float* x      = (const float*)d_in[0];  // [4096, 1024]
    const float* w_qkv  = (const float*)d_in[1];  // [3072, 1024]
    const float* w_proj = (const float*)d_in[2];  // [1024, 1024]
    const float* b_proj = (const float*)d_in[3];  // [1024]
    float* out = (float*)d_out;                   // [4096, 1024]

    (void)in_sizes; (void)n_in; (void)out_size;

    const int GEMM_SMEM = 4 * 128 * GPAD * 4;     // 73728 B
    const int ATTN_SMEM = 3 * 64 * APAD * 4;      // 55296 B
    cudaFuncSetAttribute(tc_gemm<0>, cudaFuncAttributeMaxDynamicSharedMemorySize, GEMM_SMEM);
    cudaFuncSetAttribute(tc_gemm<1>, cudaFuncAttributeMaxDynamicSharedMemorySize, GEMM_SMEM);
    cudaFuncSetAttribute(attn_kernel, cudaFuncAttributeMaxDynamicSharedMemorySize, ATTN_SMEM);

    dim3 g1(3 * CDIM / 128, NTOK / 128);   // 24 x 32
    tc_gemm<0><<<g1, 256, GEMM_SMEM>>>(x, w_qkv, nullptr, nullptr);

    dim3 g2(NTOK / 64, HEADS);             // 64 x 16
    attn_kernel<<<g2, 128, ATTN_SMEM>>>();

    dim3 g3(CDIM / 128, NTOK / 128);       // 8 x 32
    tc_gemm<1><<<g3, 256, GEMM_SMEM>>>(nullptr, w_proj, b_proj, out);
}

// round 12
// speedup vs baseline: 2.2796x; 1.1757x over previous
#include <cuda_runtime.h>
#include <math.h>
#include <stdint.h>
#include <mma.h>

using namespace nvcuda;

#define NTOK  4096
#define CDIM  1024
#define HEADS 16
#define HD    64

// Scratch (allocation-guard-safe device globals)
__device__ float g_qkv[3 * HEADS * NTOK * HD];   // [which][h][n][d]  (tf32-rounded)
__device__ float g_attn[NTOK * CDIM];            // [n][h*64+d]

// ---------------------------------------------------------------------------
// helpers
// ---------------------------------------------------------------------------
__device__ __forceinline__ float ftf32(float x) {   // round-to-nearest tf32
    uint32_t u;
    asm("cvt.rna.tf32.f32 %0, %1;" : "=r"(u) : "f"(x));
    return __uint_as_float(u);
}
__device__ __forceinline__ float4 f4tf32(float4 v) {
    v.x = ftf32(v.x); v.y = ftf32(v.y); v.z = ftf32(v.z); v.w = ftf32(v.w);
    return v;
}
__device__ __forceinline__ uint32_t smem_u32(const void* p) {
    uint32_t a;
    asm("{ .reg .u64 t; cvta.to.shared.u64 t, %1; cvt.u32.u64 %0, t; }"
        : "=r"(a) : "l"(p));
    return a;
}
__device__ __forceinline__ void cp16(uint32_t saddr, const void* g) {
    asm volatile("cp.async.cg.shared.global [%0], [%1], 16;" :: "r"(saddr), "l"(g));
}
#define CP_COMMIT() asm volatile("cp.async.commit_group;" ::: "memory")
#define CP_WAIT(n)  asm volatile("cp.async.wait_group %0;" :: "n"(n) : "memory")

// mma.sync m16n8k8 tf32: D = A*B + C   (A row-major 16x8, B col-major 8x8)
__device__ __forceinline__ void mma8(float* d, const uint32_t* a,
                                     const uint32_t* b, const float* c) {
    asm volatile(
        "mma.sync.aligned.m16n8k8.row.col.f32.tf32.tf32.f32 "
        "{%0,%1,%2,%3}, {%4,%5,%6,%7}, {%8,%9}, {%10,%11,%12,%13};"
        : "=f"(d[0]), "=f"(d[1]), "=f"(d[2]), "=f"(d[3])
        : "r"(a[0]), "r"(a[1]), "r"(a[2]), "r"(a[3]),
          "r"(b[0]), "r"(b[1]),
          "f"(c[0]), "f"(c[1]), "f"(c[2]), "f"(c[3]));
}

// ---------------------------------------------------------------------------
// wmma tf32 GEMM (validated): C[m,o] = sum_k A[m,k]*B[o,k]
// MODE 0: A = param, scatter tf32-rounded values to g_qkv.
// MODE 1: A = g_attn (device symbol!), out + bias.
// ---------------------------------------------------------------------------
#define GPAD 36

template <int MODE>
__global__ __launch_bounds__(256) void tc_gemm(const float* __restrict__ Ain,
                                               const float* __restrict__ B,
                                               const float* __restrict__ bias,
                                               float* __restrict__ out) {
    extern __shared__ float smem[];
    float* As = smem;                  // [2][128][GPAD]
    float* Bs = smem + 2 * 128 * GPAD; // [2][128][GPAD]

    const float* A = (MODE == 1) ? (const float*)g_attn : Ain;

    const int tid  = threadIdx.x;
    const int wid  = tid >> 5;
    const int lane = tid & 31;
    const int bN = blockIdx.x * 128;
    const int bM = blockIdx.y * 128;
    const int warp_m = (wid & 1) * 64;
    const int warp_n = (wid >> 1) * 32;
    const int NK = CDIM / 32;

    const int lr = tid >> 3;
    const int lc = (tid & 7) * 4;

    wmma::fragment<wmma::accumulator, 16, 16, 8, float> acc[4][2];
    #pragma unroll
    for (int mt = 0; mt < 4; mt++)
        #pragma unroll
        for (int nt = 0; nt < 2; nt++)
            wmma::fill_fragment(acc[mt][nt], 0.0f);

    #pragma unroll
    for (int i = 0; i < 4; i++) {
        int r = lr + 32 * i;
        float4 av = f4tf32(*(const float4*)(A + (size_t)(bM + r) * CDIM + lc));
        float4 bv = f4tf32(*(const float4*)(B + (size_t)(bN + r) * CDIM + lc));
        *(float4*)(As + r * GPAD + lc) = av;
        *(float4*)(Bs + r * GPAD + lc) = bv;
    }
    __syncthreads();

    for (int kt = 0; kt < NK; kt++) {
        const int b = kt & 1;
        float4 pa[4], pb[4];
        if (kt + 1 < NK) {
            #pragma unroll
            for (int i = 0; i < 4; i++) {
                int r = lr + 32 * i;
                pa[i] = *(const float4*)(A + (size_t)(bM + r) * CDIM + (kt + 1) * 32 + lc);
                pb[i] = *(const float4*)(B + (size_t)(bN + r) * CDIM + (kt + 1) * 32 + lc);
            }
        }

        const float* Ab = As + b * 128 * GPAD;
        const float* Bb = Bs + b * 128 * GPAD;
        #pragma unroll
        for (int ks = 0; ks < 4; ks++) {
            const int k0 = ks * 8;
            wmma::fragment<wmma::matrix_a, 16, 16, 8, wmma::precision::tf32, wmma::row_major> af;
            wmma::fragment<wmma::matrix_b, 16, 16, 8, wmma::precision::tf32, wmma::col_major> bf[2];
            #pragma unroll
            for (int nt = 0; nt < 2; nt++)
                wmma::load_matrix_sync(bf[nt], Bb + (warp_n + nt * 16) * GPAD + k0, GPAD);
            #pragma unroll
            for (int mt = 0; mt < 4; mt++) {
                wmma::load_matrix_sync(af, Ab + (warp_m + mt * 16) * GPAD + k0, GPAD);
                #pragma unroll
                for (int nt = 0; nt < 2; nt++)
                    wmma::mma_sync(acc[mt][nt], af, bf[nt], acc[mt][nt]);
            }
        }

        if (kt + 1 < NK) {
            const int nb = b ^ 1;
            #pragma unroll
            for (int i = 0; i < 4; i++) {
                int r = lr + 32 * i;
                *(float4*)(As + nb * 128 * GPAD + r * GPAD + lc) = f4tf32(pa[i]);
                *(float4*)(Bs + nb * 128 * GPAD + r * GPAD + lc) = f4tf32(pb[i]);
            }
        }
        __syncthreads();
    }

    float* stage = smem + wid * (16 * GPAD);
    const int o_base = bN + warp_n;
    const int row = lane >> 1;
    const int c0  = (lane & 1) * 16;

    #pragma unroll
    for (int mt = 0; mt < 4; mt++) {
        __syncwarp();
        wmma::store_matrix_sync(stage,      acc[mt][0], GPAD, wmma::mem_row_major);
        wmma::store_matrix_sync(stage + 16, acc[mt][1], GPAD, wmma::mem_row_major);
        __syncwarp();

        const int m0 = bM + warp_m + mt * 16 + row;
        if (MODE == 0) {
            const int which = o_base >> 10;
            const int h = (o_base >> 6) & 15;
            const int d0 = (o_base & 63) + c0;
            float* dst = g_qkv + ((size_t)(which * HEADS + h) * NTOK + m0) * HD + d0;
            #pragma unroll
            for (int u = 0; u < 16; u += 4)
                *(float4*)(dst + u) = f4tf32(*(const float4*)(stage + row * GPAD + c0 + u));
        } else {
            float* dst = out + (size_t)m0 * CDIM + o_base + c0;
            #pragma unroll
            for (int u = 0; u < 16; u += 4) {
                float4 v = *(const float4*)(stage + row * GPAD + c0 + u);
                float4 bb = *(const float4*)(bias + o_base + c0 + u);
                v.x += bb.x; v.y += bb.y; v.z += bb.z; v.w += bb.w;
                *(float4*)(dst + u) = v;
            }
        }
    }
}

// ---------------------------------------------------------------------------
// Causal flash attention, register-resident raw mma, cp.async double-buffered
// K/V (g_qkv holds tf32-rounded values, so tiles stream without conversion).
// Block = 128 threads (4 warps), one (head, 64-query tile).
// Strides: Ks/Ps = 68 floats (conflict-free B-fragment loads), Vs = 72.
// ---------------------------------------------------------------------------
#define KSTR 68
#define VSTR 72
#define KS_OFF(buf)  ((buf) * 64 * KSTR)
#define VS_OFF(buf)  ((buf) * 64 * VSTR)

__global__ __launch_bounds__(128) void attn_kernel() {
    extern __shared__ float smA[];
    float* Ks = smA;                          // [2][64][KSTR]
    float* Vs = smA + 2 * 64 * KSTR;          // [2][64][VSTR]
    float* Ps = smA + 2 * 64 * KSTR + 2 * 64 * VSTR;  // [64][KSTR] Q stage, then P

    const int h  = blockIdx.y;
    const int qt = gridDim.x - 1 - blockIdx.x;   // heavy tiles first
    const int tid  = threadIdx.x;
    const int wid  = tid >> 5;
    const int lane = tid & 31;
    const int g    = lane >> 2;
    const int t4   = lane & 3;

    const float* Q = g_qkv + ((size_t)(0 * HEADS + h) * NTOK + qt * 64) * HD;
    const float* K = g_qkv + ((size_t)(1 * HEADS + h) * NTOK) * HD;
    const float* V = g_qkv + ((size_t)(2 * HEADS + h) * NTOK) * HD;

    const uint32_t ks_base = smem_u32(Ks);
    const uint32_t vs_base = smem_u32(Vs);

    // K/V streaming map: 2 threads/row, 32 floats each (8 x 16B)
    const int lr   = tid >> 1;
    const int half = (tid & 1) * 32;

    // ---- issue tile 0 into buffer 0 ----
    {
        const float* Kp = K + (size_t)lr * HD + half;
        const float* Vp = V + (size_t)lr * HD + half;
        uint32_t ks = ks_base + (uint32_t)(lr * KSTR + half) * 4;
        uint32_t vs = vs_base + (uint32_t)(lr * VSTR + half) * 4;
        #pragma unroll
        for (int i = 0; i < 8; i++) cp16(ks + 16 * i, Kp + 4 * i);
        #pragma unroll
        for (int i = 0; i < 8; i++) cp16(vs + 16 * i, Vp + 4 * i);
        CP_COMMIT();
    }

    // ---- stage Q (already tf32) into Ps, hoist fragments ----
    {
        #pragma unroll
        for (int u = 0; u < 32; u += 4)
            *(float4*)(Ps + lr * KSTR + half + u) =
                *(const float4*)(Q + (size_t)lr * HD + half + u);
    }
    __syncthreads();

    uint32_t qf[8][4];
    {
        int r = wid * 16 + g;
        #pragma unroll
        for (int ks = 0; ks < 8; ks++) {
            int k0 = ks * 8 + t4;
            qf[ks][0] = __float_as_uint(Ps[r * KSTR + k0]);
            qf[ks][1] = __float_as_uint(Ps[(r + 8) * KSTR + k0]);
            qf[ks][2] = __float_as_uint(Ps[r * KSTR + k0 + 4]);
            qf[ks][3] = __float_as_uint(Ps[(r + 8) * KSTR + k0 + 4]);
        }
    }

    float o[8][4] = {};
    float mA = -1e30f, mB = -1e30f, lA = 0.f, lB = 0.f;

    const int rqA = wid * 16 + g;
    const int rqB = rqA + 8;

    for (int kt = 0; kt <= qt; kt++) {
        const int b = kt & 1;
        if (kt > 0) __syncthreads();   // prev compute done with buf b (and Ps)

        if (kt < qt) {   // issue tile kt+1 into buffer b^1
            const float* Kp = K + (size_t)((kt + 1) * 64 + lr) * HD + half;
            const float* Vp = V + (size_t)((kt + 1) * 64 + lr) * HD + half;
            uint32_t ks = ks_base + (uint32_t)(KS_OFF(b ^ 1) + lr * KSTR + half) * 4;
            uint32_t vs = vs_base + (uint32_t)(VS_OFF(b ^ 1) + lr * VSTR + half) * 4;
            #pragma unroll
            for (int i = 0; i < 8; i++) cp16(ks + 16 * i, Kp + 4 * i);
            #pragma unroll
            for (int i = 0; i < 8; i++) cp16(vs + 16 * i, Vp + 4 * i);
            CP_COMMIT();
            CP_WAIT(1);                 // tile kt complete
        } else {
            CP_WAIT(0);
        }
        __syncthreads();

        const float* Kb = Ks + KS_OFF(b);
        const float* Vb = Vs + VS_OFF(b);

        // ---- S = Q K^T ----
        float s[8][4] = {};
        #pragma unroll
        for (int ks = 0; ks < 8; ks++) {
            int k0 = ks * 8 + t4;
            #pragma unroll
            for (int nt = 0; nt < 8; nt++) {
                uint32_t bf[2];
                int j = nt * 8 + g;
                bf[0] = __float_as_uint(Kb[j * KSTR + k0]);
                bf[1] = __float_as_uint(Kb[j * KSTR + k0 + 4]);
                mma8(s[nt], qf[ks], bf, s[nt]);
            }
        }

        // scale + causal mask (diagonal tile only)
        #pragma unroll
        for (int nt = 0; nt < 8; nt++) {
            #pragma unroll
            for (int c = 0; c < 4; c++) s[nt][c] *= 0.125f;
            if (kt == qt) {
                int j0 = nt * 8 + 2 * t4;
                if (j0 > rqA)     s[nt][0] = -1e30f;
                if (j0 + 1 > rqA) s[nt][1] = -1e30f;
                if (j0 > rqB)     s[nt][2] = -1e30f;
                if (j0 + 1 > rqB) s[nt][3] = -1e30f;
            }
        }

        // ---- online softmax ----
        float mxA = -1e30f, mxB = -1e30f;
        #pragma unroll
        for (int nt = 0; nt < 8; nt++) {
            mxA = fmaxf(mxA, fmaxf(s[nt][0], s[nt][1]));
            mxB = fmaxf(mxB, fmaxf(s[nt][2], s[nt][3]));
        }
        #pragma unroll
        for (int off = 1; off < 4; off <<= 1) {
            mxA = fmaxf(mxA, __shfl_xor_sync(0xffffffffu, mxA, off));
            mxB = fmaxf(mxB, __shfl_xor_sync(0xffffffffu, mxB, off));
        }
        float mnA = fmaxf(mA, mxA), mnB = fmaxf(mB, mxB);
        float sclA = __expf(mA - mnA), sclB = __expf(mB - mnB);
        mA = mnA; mB = mnB;

        float lsA = 0.f, lsB = 0.f;
        #pragma unroll
        for (int nt = 0; nt < 8; nt++) {
            float p0 = __expf(s[nt][0] - mnA);
            float p1 = __expf(s[nt][1] - mnA);
            float p2 = __expf(s[nt][2] - mnB);
            float p3 = __expf(s[nt][3] - mnB);
            lsA += p0 + p1; lsB += p2 + p3;
            int j0 = nt * 8 + 2 * t4;
            Ps[rqA * KSTR + j0]     = ftf32(p0);
            Ps[rqA * KSTR + j0 + 1] = ftf32(p1);
            Ps[rqB * KSTR + j0]     = ftf32(p2);
            Ps[rqB * KSTR + j0 + 1] = ftf32(p3);
        }
        #pragma unroll
        for (int off = 1; off < 4; off <<= 1) {
            lsA += __shfl_xor_sync(0xffffffffu, lsA, off);
            lsB += __shfl_xor_sync(0xffffffffu, lsB, off);
        }
        lA = lA * sclA + lsA;
        lB = lB * sclB + lsB;
        #pragma unroll
        for (int nt = 0; nt < 8; nt++) {
            o[nt][0] *= sclA; o[nt][1] *= sclA;
            o[nt][2] *= sclB; o[nt][3] *= sclB;
        }
        __syncwarp();   // warp-local P strip visible

        // ---- O += P V ----
        #pragma unroll
        for (int ks = 0; ks < 8; ks++) {
            int k0 = ks * 8 + t4;
            uint32_t pf[4];
            pf[0] = __float_as_uint(Ps[rqA * KSTR + k0]);
            pf[1] = __float_as_uint(Ps[rqB * KSTR + k0]);
            pf[2] = __float_as_uint(Ps[rqA * KSTR + k0 + 4]);
            pf[3] = __float_as_uint(Ps[rqB * KSTR + k0 + 4]);
            #pragma unroll
            for (int nt = 0; nt < 8; nt++) {
                uint32_t vf[2];
                int d = nt * 8 + g;
                vf[0] = __float_as_uint(Vb[k0 * VSTR + d]);
                vf[1] = __float_as_uint(Vb[(k0 + 4) * VSTR + d]);
                mma8(o[nt], pf, vf, o[nt]);
            }
        }
    }

    // ---- normalize + write ----
    float invA = 1.f / lA, invB = 1.f / lB;
    int nA = qt * 64 + rqA, nB = qt * 64 + rqB;
    #pragma unroll
    for (int nt = 0; nt < 8; nt++) {
        int c = h * HD + nt * 8 + 2 * t4;
        *(float2*)(g_attn + (size_t)nA * CDIM + c) =
            make_float2(o[nt][0] * invA, o[nt][1] * invA);
        *(float2*)(g_attn + (size_t)nB * CDIM + c) =
            make_float2(o[nt][2] * invB, o[nt][3] * invB);
    }
}

// ---------------------------------------------------------------------------

extern "C" void kernel_launch(void* const* d_in, const int* in_sizes, int n_in,
                              void* d_out, int out_size) {
    const float* x      = (const float*)d_in[0];  // [4096, 1024]
    const float* w_qkv  = (const float*)d_in[1];  // [3072, 1024]
    const float* w_proj = (const float*)d_in[2];  // [1024, 1024]
    const float* b_proj = (const float*)d_in[3];  // [1024]
    float* out = (float*)d_out;                   // [4096, 1024]

    (void)in_sizes; (void)n_in; (void)out_size;

    const int GEMM_SMEM = 4 * 128 * GPAD * 4;                       // 73728 B
    const int ATTN_SMEM = (2 * 64 * KSTR + 2 * 64 * VSTR + 64 * KSTR) * 4;  // 89088 B
    cudaFuncSetAttribute(tc_gemm<0>, cudaFuncAttributeMaxDynamicSharedMemorySize, GEMM_SMEM);
    cudaFuncSetAttribute(tc_gemm<1>, cudaFuncAttributeMaxDynamicSharedMemorySize, GEMM_SMEM);
    cudaFuncSetAttribute(attn_kernel, cudaFuncAttributeMaxDynamicSharedMemorySize, ATTN_SMEM);

    dim3 g1(3 * CDIM / 128, NTOK / 128);   // 24 x 32
    tc_gemm<0><<<g1, 256, GEMM_SMEM>>>(x, w_qkv, nullptr, nullptr);

    dim3 g2(NTOK / 64, HEADS);             // 64 x 16
    attn_kernel<<<g2, 128, ATTN_SMEM>>>();

    dim3 g3(CDIM / 128, NTOK / 128);       // 8 x 32
    tc_gemm<1><<<g3, 256, GEMM_SMEM>>>(nullptr, w_proj, b_proj, out);
}

// round 15
// speedup vs baseline: 2.5057x; 1.0992x over previous
#include <cuda_runtime.h>
#include <math.h>
#include <stdint.h>
#include <mma.h>

using namespace nvcuda;

#define NTOK  4096
#define CDIM  1024
#define HEADS 16
#define HD    64

// Scratch (allocation-guard-safe device globals)
__device__ float g_qkv[3 * HEADS * NTOK * HD];   // [which][h][n][d]  (tf32-rounded)
__device__ float g_attn[NTOK * CDIM];            // [n][h*64+d]       (tf32-rounded)
__device__ float g_xt[NTOK * CDIM];              // tf32-rounded x
__device__ float g_wq[3 * CDIM * CDIM];          // tf32-rounded w_qkv
__device__ float g_wp[CDIM * CDIM];              // tf32-rounded w_proj

// ---------------------------------------------------------------------------
// helpers
// ---------------------------------------------------------------------------
__device__ __forceinline__ float ftf32(float x) {   // round-to-nearest tf32
    uint32_t u;
    asm("cvt.rna.tf32.f32 %0, %1;" : "=r"(u) : "f"(x));
    return __uint_as_float(u);
}
__device__ __forceinline__ float4 f4tf32(float4 v) {
    v.x = ftf32(v.x); v.y = ftf32(v.y); v.z = ftf32(v.z); v.w = ftf32(v.w);
    return v;
}
__device__ __forceinline__ uint32_t smem_u32(const void* p) {
    uint32_t a;
    asm("{ .reg .u64 t; cvta.to.shared.u64 t, %1; cvt.u32.u64 %0, t; }"
        : "=r"(a) : "l"(p));
    return a;
}
__device__ __forceinline__ void cp16(uint32_t saddr, const void* g) {
    asm volatile("cp.async.cg.shared.global [%0], [%1], 16;" :: "r"(saddr), "l"(g));
}
#define CP_COMMIT() asm volatile("cp.async.commit_group;" ::: "memory")
#define CP_WAIT(n)  asm volatile("cp.async.wait_group %0;" :: "n"(n) : "memory")

// mma.sync m16n8k8 tf32: D = A*B + C   (A row-major 16x8, B col-major 8x8)
__device__ __forceinline__ void mma8(float* d, const uint32_t* a,
                                     const uint32_t* b, const float* c) {
    asm volatile(
        "mma.sync.aligned.m16n8k8.row.col.f32.tf32.tf32.f32 "
        "{%0,%1,%2,%3}, {%4,%5,%6,%7}, {%8,%9}, {%10,%11,%12,%13};"
        : "=f"(d[0]), "=f"(d[1]), "=f"(d[2]), "=f"(d[3])
        : "r"(a[0]), "r"(a[1]), "r"(a[2]), "r"(a[3]),
          "r"(b[0]), "r"(b[1]),
          "f"(c[0]), "f"(c[1]), "f"(c[2]), "f"(c[3]));
}

// ---------------------------------------------------------------------------
// prep: tf32-round x / w_qkv / w_proj into device globals (float4 grain)
// ---------------------------------------------------------------------------
__global__ __launch_bounds__(256) void prep_kernel(const float* __restrict__ x,
                                                   const float* __restrict__ wq,
                                                   const float* __restrict__ wp) {
    const size_t NX = (size_t)NTOK * CDIM / 4;
    const size_t NQ = (size_t)3 * CDIM * CDIM / 4;
    const size_t NP = (size_t)CDIM * CDIM / 4;
    size_t i = (size_t)blockIdx.x * blockDim.x + threadIdx.x;
    if (i < NX)
        ((float4*)g_xt)[i] = f4tf32(((const float4*)x)[i]);
    else if (i < NX + NQ)
        ((float4*)g_wq)[i - NX] = f4tf32(((const float4*)wq)[i - NX]);
    else if (i < NX + NQ + NP)
        ((float4*)g_wp)[i - NX - NQ] = f4tf32(((const float4*)wp)[i - NX - NQ]);
}

// ---------------------------------------------------------------------------
// wmma tf32 GEMM, cp.async double-buffered (inputs pre-rounded to tf32):
// C[m,o] = sum_k A[m,k]*B[o,k]
// MODE 0: A=g_xt, B=g_wq, scatter tf32-rounded to g_qkv.
// MODE 1: A=g_attn, B=g_wp, out + bias.
// ---------------------------------------------------------------------------
#define GPAD 36

template <int MODE>
__global__ __launch_bounds__(256, 2) void tc_gemm(const float* __restrict__ bias,
                                                  float* __restrict__ out) {
    extern __shared__ float smem[];
    float* As = smem;                  // [2][128][GPAD]
    float* Bs = smem + 2 * 128 * GPAD; // [2][128][GPAD]

    const float* A = (MODE == 0) ? (const float*)g_xt : (const float*)g_attn;
    const float* B = (MODE == 0) ? (const float*)g_wq : (const float*)g_wp;

    const int tid  = threadIdx.x;
    const int wid  = tid >> 5;
    const int lane = tid & 31;
    const int bN = blockIdx.x * 128;
    const int bM = blockIdx.y * 128;
    const int warp_m = (wid & 1) * 64;
    const int warp_n = (wid >> 1) * 32;
    const int NK = CDIM / 32;

    const int lr = tid >> 3;          // 0..31
    const int lc = (tid & 7) * 4;     // 0..28

    const uint32_t as_base = smem_u32(As);
    const uint32_t bs_base = smem_u32(Bs);

    wmma::fragment<wmma::accumulator, 16, 16, 8, float> acc[4][2];
    #pragma unroll
    for (int mt = 0; mt < 4; mt++)
        #pragma unroll
        for (int nt = 0; nt < 2; nt++)
            wmma::fill_fragment(acc[mt][nt], 0.0f);

    // issue tile 0 -> buffer 0
    #pragma unroll
    for (int i = 0; i < 4; i++) {
        int r = lr + 32 * i;
        cp16(as_base + (uint32_t)(r * GPAD + lc) * 4, A + (size_t)(bM + r) * CDIM + lc);
        cp16(bs_base + (uint32_t)(r * GPAD + lc) * 4, B + (size_t)(bN + r) * CDIM + lc);
    }
    CP_COMMIT();

    for (int kt = 0; kt < NK; kt++) {
        const int b = kt & 1;
        if (kt + 1 < NK) {
            const int nb = b ^ 1;
            #pragma unroll
            for (int i = 0; i < 4; i++) {
                int r = lr + 32 * i;
                cp16(as_base + (uint32_t)(nb * 128 * GPAD + r * GPAD + lc) * 4,
                     A + (size_t)(bM + r) * CDIM + (kt + 1) * 32 + lc);
                cp16(bs_base + (uint32_t)(nb * 128 * GPAD + r * GPAD + lc) * 4,
                     B + (size_t)(bN + r) * CDIM + (kt + 1) * 32 + lc);
            }
            CP_COMMIT();
            CP_WAIT(1);
        } else {
            CP_WAIT(0);
        }
        __syncthreads();

        const float* Ab = As + b * 128 * GPAD;
        const float* Bb = Bs + b * 128 * GPAD;
        #pragma unroll
        for (int ks = 0; ks < 4; ks++) {
            const int k0 = ks * 8;
            wmma::fragment<wmma::matrix_a, 16, 16, 8, wmma::precision::tf32, wmma::row_major> af;
            wmma::fragment<wmma::matrix_b, 16, 16, 8, wmma::precision::tf32, wmma::col_major> bf[2];
            #pragma unroll
            for (int nt = 0; nt < 2; nt++)
                wmma::load_matrix_sync(bf[nt], Bb + (warp_n + nt * 16) * GPAD + k0, GPAD);
            #pragma unroll
            for (int mt = 0; mt < 4; mt++) {
                wmma::load_matrix_sync(af, Ab + (warp_m + mt * 16) * GPAD + k0, GPAD);
                #pragma unroll
                for (int nt = 0; nt < 2; nt++)
                    wmma::mma_sync(acc[mt][nt], af, bf[nt], acc[mt][nt]);
            }
        }
        __syncthreads();   // compute done before next iter overwrites buf b
    }

    // ---- epilogue: store_matrix_sync -> per-warp smem stage -> gmem ----
    float* stage = smem + wid * (16 * GPAD);
    const int o_base = bN + warp_n;
    const int row = lane >> 1;
    const int c0  = (lane & 1) * 16;

    #pragma unroll
    for (int mt = 0; mt < 4; mt++) {
        __syncwarp();
        wmma::store_matrix_sync(stage,      acc[mt][0], GPAD, wmma::mem_row_major);
        wmma::store_matrix_sync(stage + 16, acc[mt][1], GPAD, wmma::mem_row_major);
        __syncwarp();

        const int m0 = bM + warp_m + mt * 16 + row;
        if (MODE == 0) {
            const int which = o_base >> 10;
            const int h = (o_base >> 6) & 15;
            const int d0 = (o_base & 63) + c0;
            float* dst = g_qkv + ((size_t)(which * HEADS + h) * NTOK + m0) * HD + d0;
            #pragma unroll
            for (int u = 0; u < 16; u += 4)
                *(float4*)(dst + u) = f4tf32(*(const float4*)(stage + row * GPAD + c0 + u));
        } else {
            float* dst = out + (size_t)m0 * CDIM + o_base + c0;
            #pragma unroll
            for (int u = 0; u < 16; u += 4) {
                float4 v = *(const float4*)(stage + row * GPAD + c0 + u);
                float4 bb = *(const float4*)(bias + o_base + c0 + u);
                v.x += bb.x; v.y += bb.y; v.z += bb.z; v.w += bb.w;
                *(float4*)(dst + u) = v;
            }
        }
    }
}

// ---------------------------------------------------------------------------
// Causal flash attention, register-resident raw mma, cp.async double-buffered
// K/V (unchanged from round 12 except tf32-rounding the g_attn write).
// ---------------------------------------------------------------------------
#define KSTR 68
#define VSTR 72
#define KS_OFF(buf)  ((buf) * 64 * KSTR)
#define VS_OFF(buf)  ((buf) * 64 * VSTR)

__global__ __launch_bounds__(128) void attn_kernel() {
    extern __shared__ float smA[];
    float* Ks = smA;                          // [2][64][KSTR]
    float* Vs = smA + 2 * 64 * KSTR;          // [2][64][VSTR]
    float* Ps = smA + 2 * 64 * KSTR + 2 * 64 * VSTR;  // [64][KSTR]

    const int h  = blockIdx.y;
    const int qt = gridDim.x - 1 - blockIdx.x;
    const int tid  = threadIdx.x;
    const int wid  = tid >> 5;
    const int lane = tid & 31;
    const int g    = lane >> 2;
    const int t4   = lane & 3;

    const float* Q = g_qkv + ((size_t)(0 * HEADS + h) * NTOK + qt * 64) * HD;
    const float* K = g_qkv + ((size_t)(1 * HEADS + h) * NTOK) * HD;
    const float* V = g_qkv + ((size_t)(2 * HEADS + h) * NTOK) * HD;

    const uint32_t ks_base = smem_u32(Ks);
    const uint32_t vs_base = smem_u32(Vs);

    const int lr   = tid >> 1;
    const int half = (tid & 1) * 32;

    {
        const float* Kp = K + (size_t)lr * HD + half;
        const float* Vp = V + (size_t)lr * HD + half;
        uint32_t ks = ks_base + (uint32_t)(lr * KSTR + half) * 4;
        uint32_t vs = vs_base + (uint32_t)(lr * VSTR + half) * 4;
        #pragma unroll
        for (int i = 0; i < 8; i++) cp16(ks + 16 * i, Kp + 4 * i);
        #pragma unroll
        for (int i = 0; i < 8; i++) cp16(vs + 16 * i, Vp + 4 * i);
        CP_COMMIT();
    }

    {
        #pragma unroll
        for (int u = 0; u < 32; u += 4)
            *(float4*)(Ps + lr * KSTR + half + u) =
                *(const float4*)(Q + (size_t)lr * HD + half + u);
    }
    __syncthreads();

    uint32_t qf[8][4];
    {
        int r = wid * 16 + g;
        #pragma unroll
        for (int ks = 0; ks < 8; ks++) {
            int k0 = ks * 8 + t4;
            qf[ks][0] = __float_as_uint(Ps[r * KSTR + k0]);
            qf[ks][1] = __float_as_uint(Ps[(r + 8) * KSTR + k0]);
            qf[ks][2] = __float_as_uint(Ps[r * KSTR + k0 + 4]);
            qf[ks][3] = __float_as_uint(Ps[(r + 8) * KSTR + k0 + 4]);
        }
    }

    float o[8][4] = {};
    float mA = -1e30f, mB = -1e30f, lA = 0.f, lB = 0.f;

    const int rqA = wid * 16 + g;
    const int rqB = rqA + 8;

    for (int kt = 0; kt <= qt; kt++) {
        const int b = kt & 1;
        if (kt > 0) __syncthreads();

        if (kt < qt) {
            const float* Kp = K + (size_t)((kt + 1) * 64 + lr) * HD + half;
            const float* Vp = V + (size_t)((kt + 1) * 64 + lr) * HD + half;
            uint32_t ks = ks_base + (uint32_t)(KS_OFF(b ^ 1) + lr * KSTR + half) * 4;
            uint32_t vs = vs_base + (uint32_t)(VS_OFF(b ^ 1) + lr * VSTR + half) * 4;
            #pragma unroll
            for (int i = 0; i < 8; i++) cp16(ks + 16 * i, Kp + 4 * i);
            #pragma unroll
            for (int i = 0; i < 8; i++) cp16(vs + 16 * i, Vp + 4 * i);
            CP_COMMIT();
            CP_WAIT(1);
        } else {
            CP_WAIT(0);
        }
        __syncthreads();

        const float* Kb = Ks + KS_OFF(b);
        const float* Vb = Vs + VS_OFF(b);

        float s[8][4] = {};
        #pragma unroll
        for (int ks = 0; ks < 8; ks++) {
            int k0 = ks * 8 + t4;
            #pragma unroll
            for (int nt = 0; nt < 8; nt++) {
                uint32_t bf[2];
                int j = nt * 8 + g;
                bf[0] = __float_as_uint(Kb[j * KSTR + k0]);
                bf[1] = __float_as_uint(Kb[j * KSTR + k0 + 4]);
                mma8(s[nt], qf[ks], bf, s[nt]);
            }
        }

        #pragma unroll
        for (int nt = 0; nt < 8; nt++) {
            #pragma unroll
            for (int c = 0; c < 4; c++) s[nt][c] *= 0.125f;
            if (kt == qt) {
                int j0 = nt * 8 + 2 * t4;
                if (j0 > rqA)     s[nt][0] = -1e30f;
                if (j0 + 1 > rqA) s[nt][1] = -1e30f;
                if (j0 > rqB)     s[nt][2] = -1e30f;
                if (j0 + 1 > rqB) s[nt][3] = -1e30f;
            }
        }

        float mxA = -1e30f, mxB = -1e30f;
        #pragma unroll
        for (int nt = 0; nt < 8; nt++) {
            mxA = fmaxf(mxA, fmaxf(s[nt][0], s[nt][1]));
            mxB = fmaxf(mxB, fmaxf(s[nt][2], s[nt][3]));
        }
        #pragma unroll
        for (int off = 1; off < 4; off <<= 1) {
            mxA = fmaxf(mxA, __shfl_xor_sync(0xffffffffu, mxA, off));
            mxB = fmaxf(mxB, __shfl_xor_sync(0xffffffffu, mxB, off));
        }
        float mnA = fmaxf(mA, mxA), mnB = fmaxf(mB, mxB);
        float sclA = __expf(mA - mnA), sclB = __expf(mB - mnB);
        mA = mnA; mB = mnB;

        float lsA = 0.f, lsB = 0.f;
        #pragma unroll
        for (int nt = 0; nt < 8; nt++) {
            float p0 = __expf(s[nt][0] - mnA);
            float p1 = __expf(s[nt][1] - mnA);
            float p2 = __expf(s[nt][2] - mnB);
            float p3 = __expf(s[nt][3] - mnB);
            lsA += p0 + p1; lsB += p2 + p3;
            int j0 = nt * 8 + 2 * t4;
            Ps[rqA * KSTR + j0]     = ftf32(p0);
            Ps[rqA * KSTR + j0 + 1] = ftf32(p1);
            Ps[rqB * KSTR + j0]     = ftf32(p2);
            Ps[rqB * KSTR + j0 + 1] = ftf32(p3);
        }
        #pragma unroll
        for (int off = 1; off < 4; off <<= 1) {
            lsA += __shfl_xor_sync(0xffffffffu, lsA, off);
            lsB += __shfl_xor_sync(0xffffffffu, lsB, off);
        }
        lA = lA * sclA + lsA;
        lB = lB * sclB + lsB;
        #pragma unroll
        for (int nt = 0; nt < 8; nt++) {
            o[nt][0] *= sclA; o[nt][1] *= sclA;
            o[nt][2] *= sclB; o[nt][3] *= sclB;
        }
        __syncwarp();

        #pragma unroll
        for (int ks = 0; ks < 8; ks++) {
            int k0 = ks * 8 + t4;
            uint32_t pf[4];
            pf[0] = __float_as_uint(Ps[rqA * KSTR + k0]);
            pf[1] = __float_as_uint(Ps[rqB * KSTR + k0]);
            pf[2] = __float_as_uint(Ps[rqA * KSTR + k0 + 4]);
            pf[3] = __float_as_uint(Ps[rqB * KSTR + k0 + 4]);
            #pragma unroll
            for (int nt = 0; nt < 8; nt++) {
                uint32_t vf[2];
                int d = nt * 8 + g;
                vf[0] = __float_as_uint(Vb[k0 * VSTR + d]);
                vf[1] = __float_as_uint(Vb[(k0 + 4) * VSTR + d]);
                mma8(o[nt], pf, vf, o[nt]);
            }
        }
    }

    float invA = 1.f / lA, invB = 1.f / lB;
    int nA = qt * 64 + rqA, nB = qt * 64 + rqB;
    #pragma unroll
    for (int nt = 0; nt < 8; nt++) {
        int c = h * HD + nt * 8 + 2 * t4;
        *(float2*)(g_attn + (size_t)nA * CDIM + c) =
            make_float2(ftf32(o[nt][0] * invA), ftf32(o[nt][1] * invA));
        *(float2*)(g_attn + (size_t)nB * CDIM + c) =
            make_float2(ftf32(o[nt][2] * invB), ftf32(o[nt][3] * invB));
    }
}

// ---------------------------------------------------------------------------

extern "C" void kernel_launch(void* const* d_in, const int* in_sizes, int n_in,
                              void* d_out, int out_size) {
    const float* x      = (const float*)d_in[0];  // [4096, 1024]
    const float* w_qkv  = (const float*)d_in[1];  // [3072, 1024]
    const float* w_proj = (const float*)d_in[2];  // [1024, 1024]
    const float* b_proj = (const float*)d_in[3];  // [1024]
    float* out = (float*)d_out;                   // [4096, 1024]

    (void)in_sizes; (void)n_in; (void)out_size;

    const int GEMM_SMEM = 4 * 128 * GPAD * 4;                       // 73728 B
    const int ATTN_SMEM = (2 * 64 * KSTR + 2 * 64 * VSTR + 64 * KSTR) * 4;  // 89088 B
    cudaFuncSetAttribute(tc_gemm<0>, cudaFuncAttributeMaxDynamicSharedMemorySize, GEMM_SMEM);
    cudaFuncSetAttribute(tc_gemm<1>, cudaFuncAttributeMaxDynamicSharedMemorySize, GEMM_SMEM);
    cudaFuncSetAttribute(attn_kernel, cudaFuncAttributeMaxDynamicSharedMemorySize, ATTN_SMEM);

    const size_t NPREP = ((size_t)NTOK * CDIM + 3 * CDIM * CDIM + CDIM * CDIM) / 4;
    prep_kernel<<<(unsigned)((NPREP + 255) / 256), 256>>>(x, w_qkv, w_proj);

    dim3 g1(3 * CDIM / 128, NTOK / 128);   // 24 x 32
    tc_gemm<0><<<g1, 256, GEMM_SMEM>>>(nullptr, nullptr);

    dim3 g2(NTOK / 64, HEADS);             // 64 x 16
    attn_kernel<<<g2, 128, ATTN_SMEM>>>();

    dim3 g3(CDIM / 128, NTOK / 128);       // 8 x 32
    tc_gemm<1><<<g3, 256, GEMM_SMEM>>>(b_proj, out);
}

// round 16
// speedup vs baseline: 2.6293x; 1.0494x over previous
#include <cuda_runtime.h>
#include <math.h>
#include <stdint.h>
#include <mma.h>

using namespace nvcuda;

#define NTOK  4096
#define CDIM  1024
#define HEADS 16
#define HD    64

// Scratch (allocation-guard-safe device globals)
__device__ float g_qkv[3 * HEADS * NTOK * HD];   // [which][h][n][d]  (tf32-rounded)
__device__ float g_attn[NTOK * CDIM];            // [n][h*64+d]       (tf32-rounded)
__device__ float g_xt[NTOK * CDIM];              // tf32-rounded x
__device__ float g_wq[3 * CDIM * CDIM];          // tf32-rounded w_qkv
__device__ float g_wp[CDIM * CDIM];              // tf32-rounded w_proj

// ---------------------------------------------------------------------------
// helpers
// ---------------------------------------------------------------------------
__device__ __forceinline__ float ftf32(float x) {   // round-to-nearest tf32
    uint32_t u;
    asm("cvt.rna.tf32.f32 %0, %1;" : "=r"(u) : "f"(x));
    return __uint_as_float(u);
}
__device__ __forceinline__ float4 f4tf32(float4 v) {
    v.x = ftf32(v.x); v.y = ftf32(v.y); v.z = ftf32(v.z); v.w = ftf32(v.w);
    return v;
}
__device__ __forceinline__ uint32_t smem_u32(const void* p) {
    uint32_t a;
    asm("{ .reg .u64 t; cvta.to.shared.u64 t, %1; cvt.u32.u64 %0, t; }"
        : "=r"(a) : "l"(p));
    return a;
}
__device__ __forceinline__ void cp16(uint32_t saddr, const void* g) {
    asm volatile("cp.async.cg.shared.global [%0], [%1], 16;" :: "r"(saddr), "l"(g));
}
#define CP_COMMIT() asm volatile("cp.async.commit_group;" ::: "memory")
#define CP_WAIT(n)  asm volatile("cp.async.wait_group %0;" :: "n"(n) : "memory")

// mma.sync m16n8k8 tf32: D = A*B + C   (A row-major 16x8, B col-major 8x8)
__device__ __forceinline__ void mma8(float* d, const uint32_t* a,
                                     const uint32_t* b, const float* c) {
    asm volatile(
        "mma.sync.aligned.m16n8k8.row.col.f32.tf32.tf32.f32 "
        "{%0,%1,%2,%3}, {%4,%5,%6,%7}, {%8,%9}, {%10,%11,%12,%13};"
        : "=f"(d[0]), "=f"(d[1]), "=f"(d[2]), "=f"(d[3])
        : "r"(a[0]), "r"(a[1]), "r"(a[2]), "r"(a[3]),
          "r"(b[0]), "r"(b[1]),
          "f"(c[0]), "f"(c[1]), "f"(c[2]), "f"(c[3]));
}

// ---------------------------------------------------------------------------
// prep: tf32-round x / w_qkv / w_proj into device globals (float4 grain)
// ---------------------------------------------------------------------------
__global__ __launch_bounds__(256) void prep_kernel(const float* __restrict__ x,
                                                   const float* __restrict__ wq,
                                                   const float* __restrict__ wp) {
    const size_t NX = (size_t)NTOK * CDIM / 4;
    const size_t NQ = (size_t)3 * CDIM * CDIM / 4;
    const size_t NP = (size_t)CDIM * CDIM / 4;
    size_t i = (size_t)blockIdx.x * blockDim.x + threadIdx.x;
    if (i < NX)
        ((float4*)g_xt)[i] = f4tf32(((const float4*)x)[i]);
    else if (i < NX + NQ)
        ((float4*)g_wq)[i - NX] = f4tf32(((const float4*)wq)[i - NX]);
    else if (i < NX + NQ + NP)
        ((float4*)g_wp)[i - NX - NQ] = f4tf32(((const float4*)wp)[i - NX - NQ]);
}

// ---------------------------------------------------------------------------
// wmma tf32 GEMM, cp.async double-buffered (inputs pre-rounded to tf32):
// C[m,o] = sum_k A[m,k]*B[o,k]
// MODE 0: A=g_xt, B=g_wq, scatter tf32-rounded to g_qkv.
// MODE 1: A=g_attn, B=g_wp, out + bias.
// ---------------------------------------------------------------------------
#define GPAD 36

template <int MODE>
__global__ __launch_bounds__(256, 2) void tc_gemm(const float* __restrict__ bias,
                                                  float* __restrict__ out) {
    extern __shared__ float smem[];
    float* As = smem;                  // [2][128][GPAD]
    float* Bs = smem + 2 * 128 * GPAD; // [2][128][GPAD]

    const float* A = (MODE == 0) ? (const float*)g_xt : (const float*)g_attn;
    const float* B = (MODE == 0) ? (const float*)g_wq : (const float*)g_wp;

    const int tid  = threadIdx.x;
    const int wid  = tid >> 5;
    const int lane = tid & 31;
    const int bN = blockIdx.x * 128;
    const int bM = blockIdx.y * 128;
    const int warp_m = (wid & 1) * 64;
    const int warp_n = (wid >> 1) * 32;
    const int NK = CDIM / 32;

    const int lr = tid >> 3;          // 0..31
    const int lc = (tid & 7) * 4;     // 0..28

    const uint32_t as_base = smem_u32(As);
    const uint32_t bs_base = smem_u32(Bs);

    wmma::fragment<wmma::accumulator, 16, 16, 8, float> acc[4][2];
    #pragma unroll
    for (int mt = 0; mt < 4; mt++)
        #pragma unroll
        for (int nt = 0; nt < 2; nt++)
            wmma::fill_fragment(acc[mt][nt], 0.0f);

    // issue tile 0 -> buffer 0
    #pragma unroll
    for (int i = 0; i < 4; i++) {
        int r = lr + 32 * i;
        cp16(as_base + (uint32_t)(r * GPAD + lc) * 4, A + (size_t)(bM + r) * CDIM + lc);
        cp16(bs_base + (uint32_t)(r * GPAD + lc) * 4, B + (size_t)(bN + r) * CDIM + lc);
    }
    CP_COMMIT();

    for (int kt = 0; kt < NK; kt++) {
        const int b = kt & 1;
        if (kt + 1 < NK) {
            const int nb = b ^ 1;
            #pragma unroll
            for (int i = 0; i < 4; i++) {
                int r = lr + 32 * i;
                cp16(as_base + (uint32_t)(nb * 128 * GPAD + r * GPAD + lc) * 4,
                     A + (size_t)(bM + r) * CDIM + (kt + 1) * 32 + lc);
                cp16(bs_base + (uint32_t)(nb * 128 * GPAD + r * GPAD + lc) * 4,
                     B + (size_t)(bN + r) * CDIM + (kt + 1) * 32 + lc);
            }
            CP_COMMIT();
            CP_WAIT(1);
        } else {
            CP_WAIT(0);
        }
        __syncthreads();

        const float* Ab = As + b * 128 * GPAD;
        const float* Bb = Bs + b * 128 * GPAD;
        #pragma unroll
        for (int ks = 0; ks < 4; ks++) {
            const int k0 = ks * 8;
            wmma::fragment<wmma::matrix_a, 16, 16, 8, wmma::precision::tf32, wmma::row_major> af;
            wmma::fragment<wmma::matrix_b, 16, 16, 8, wmma::precision::tf32, wmma::col_major> bf[2];
            #pragma unroll
            for (int nt = 0; nt < 2; nt++)
                wmma::load_matrix_sync(bf[nt], Bb + (warp_n + nt * 16) * GPAD + k0, GPAD);
            #pragma unroll
            for (int mt = 0; mt < 4; mt++) {
                wmma::load_matrix_sync(af, Ab + (warp_m + mt * 16) * GPAD + k0, GPAD);
                #pragma unroll
                for (int nt = 0; nt < 2; nt++)
                    wmma::mma_sync(acc[mt][nt], af, bf[nt], acc[mt][nt]);
            }
        }
        __syncthreads();   // compute done before next iter overwrites buf b
    }

    // ---- epilogue: store_matrix_sync -> per-warp smem stage -> gmem ----
    float* stage = smem + wid * (16 * GPAD);
    const int o_base = bN + warp_n;
    const int row = lane >> 1;
    const int c0  = (lane & 1) * 16;

    #pragma unroll
    for (int mt = 0; mt < 4; mt++) {
        __syncwarp();
        wmma::store_matrix_sync(stage,      acc[mt][0], GPAD, wmma::mem_row_major);
        wmma::store_matrix_sync(stage + 16, acc[mt][1], GPAD, wmma::mem_row_major);
        __syncwarp();

        const int m0 = bM + warp_m + mt * 16 + row;
        if (MODE == 0) {
            const int which = o_base >> 10;
            const int h = (o_base >> 6) & 15;
            const int d0 = (o_base & 63) + c0;
            float* dst = g_qkv + ((size_t)(which * HEADS + h) * NTOK + m0) * HD + d0;
            #pragma unroll
            for (int u = 0; u < 16; u += 4)
                *(float4*)(dst + u) = f4tf32(*(const float4*)(stage + row * GPAD + c0 + u));
        } else {
            float* dst = out + (size_t)m0 * CDIM + o_base + c0;
            #pragma unroll
            for (int u = 0; u < 16; u += 4) {
                float4 v = *(const float4*)(stage + row * GPAD + c0 + u);
                float4 bb = *(const float4*)(bias + o_base + c0 + u);
                v.x += bb.x; v.y += bb.y; v.z += bb.z; v.w += bb.w;
                *(float4*)(dst + u) = v;
            }
        }
    }
}

// ---------------------------------------------------------------------------
// Causal flash attention, register-resident raw mma, cp.async double-buffered.
// Block = 256 threads (8 warps), one (head, 128-query tile); KV tiles of 64.
// Warp w owns query rows 16w..16w+15. Q pre-scaled by 0.125 at staging.
// V stored with column swizzle d^((j&3)*8) -> conflict-free fragment loads.
// ---------------------------------------------------------------------------
#define KSTR 68
#define VSTR 68
#define KS_OFF(buf)  ((buf) * 64 * KSTR)
#define VS_OFF(buf)  ((buf) * 64 * VSTR)

__global__ __launch_bounds__(256, 2) void attn_kernel() {
    extern __shared__ float smA[];
    float* Ks = smA;                          // [2][64][KSTR]
    float* Vs = smA + 2 * 64 * KSTR;          // [2][64][VSTR]  (d-swizzled)
    float* Ps = smA + 2 * 64 * KSTR + 2 * 64 * VSTR;  // [128][KSTR] Q stage, then P

    const int h  = blockIdx.y;
    const int qt = gridDim.x - 1 - blockIdx.x;   // heavy tiles first
    const int tid  = threadIdx.x;
    const int wid  = tid >> 5;
    const int lane = tid & 31;
    const int g    = lane >> 2;
    const int t4   = lane & 3;

    const float* Q = g_qkv + ((size_t)(0 * HEADS + h) * NTOK + qt * 128) * HD;
    const float* K = g_qkv + ((size_t)(1 * HEADS + h) * NTOK) * HD;
    const float* V = g_qkv + ((size_t)(2 * HEADS + h) * NTOK) * HD;

    const uint32_t ks_base = smem_u32(Ks);
    const uint32_t vs_base = smem_u32(Vs);

    // K/V streaming map: 4 threads/row (64 rows), 16 floats each (4 x 16B)
    const int lr4 = tid >> 2;            // 0..63
    const int qtr = (tid & 3) * 16;      // 0,16,32,48
    const int vsw = (lr4 & 3) * 8;       // V column swizzle for this row

    // ---- issue tile 0 into buffer 0 ----
    {
        const float* Kp = K + (size_t)lr4 * HD + qtr;
        const float* Vp = V + (size_t)lr4 * HD + qtr;
        #pragma unroll
        for (int i = 0; i < 4; i++) {
            cp16(ks_base + (uint32_t)(lr4 * KSTR + qtr + 4 * i) * 4, Kp + 4 * i);
            cp16(vs_base + (uint32_t)(lr4 * VSTR + ((qtr + 4 * i) ^ vsw)) * 4, Vp + 4 * i);
        }
        CP_COMMIT();
    }

    // ---- stage Q * 0.125 (exact) into Ps, hoist fragments ----
    {
        int r = tid >> 1;                 // 0..127
        int half = (tid & 1) * 32;
        #pragma unroll
        for (int u = 0; u < 32; u += 4) {
            float4 v = *(const float4*)(Q + (size_t)r * HD + half + u);
            v.x *= 0.125f; v.y *= 0.125f; v.z *= 0.125f; v.w *= 0.125f;
            *(float4*)(Ps + r * KSTR + half + u) = v;
        }
    }
    __syncthreads();

    uint32_t qf[8][4];
    {
        int r = wid * 16 + g;
        #pragma unroll
        for (int ks = 0; ks < 8; ks++) {
            int k0 = ks * 8 + t4;
            qf[ks][0] = __float_as_uint(Ps[r * KSTR + k0]);
            qf[ks][1] = __float_as_uint(Ps[(r + 8) * KSTR + k0]);
            qf[ks][2] = __float_as_uint(Ps[r * KSTR + k0 + 4]);
            qf[ks][3] = __float_as_uint(Ps[(r + 8) * KSTR + k0 + 4]);
        }
    }

    float o[8][4] = {};
    float mA = -1e30f, mB = -1e30f, lA = 0.f, lB = 0.f;

    const int rqA = wid * 16 + g;        // 0..127
    const int rqB = rqA + 8;

    const int nkt = 2 * qt + 2;
    for (int kt = 0; kt < nkt; kt++) {
        const int b = kt & 1;
        if (kt > 0) __syncthreads();     // prev compute done with buf b

        if (kt + 1 < nkt) {              // issue tile kt+1 into buffer b^1
            const float* Kp = K + (size_t)((kt + 1) * 64 + lr4) * HD + qtr;
            const float* Vp = V + (size_t)((kt + 1) * 64 + lr4) * HD + qtr;
            #pragma unroll
            for (int i = 0; i < 4; i++) {
                cp16(ks_base + (uint32_t)(KS_OFF(b ^ 1) + lr4 * KSTR + qtr + 4 * i) * 4,
                     Kp + 4 * i);
                cp16(vs_base + (uint32_t)(VS_OFF(b ^ 1) + lr4 * VSTR + ((qtr + 4 * i) ^ vsw)) * 4,
                     Vp + 4 * i);
            }
            CP_COMMIT();
            CP_WAIT(1);
        } else {
            CP_WAIT(0);
        }
        __syncthreads();

        const float* Kb = Ks + KS_OFF(b);
        const float* Vb = Vs + VS_OFF(b);

        // ---- S = (Q/8) K^T ----
        float s[8][4] = {};
        #pragma unroll
        for (int ks = 0; ks < 8; ks++) {
            int k0 = ks * 8 + t4;
            #pragma unroll
            for (int nt = 0; nt < 8; nt++) {
                uint32_t bf[2];
                int j = nt * 8 + g;
                bf[0] = __float_as_uint(Kb[j * KSTR + k0]);
                bf[1] = __float_as_uint(Kb[j * KSTR + k0 + 4]);
                mma8(s[nt], qf[ks], bf, s[nt]);
            }
        }

        // ---- causal mask (last two tiles only) ----
        if (kt >= 2 * qt) {
            const int joff = (kt - 2 * qt) * 64;
            #pragma unroll
            for (int nt = 0; nt < 8; nt++) {
                int j0 = joff + nt * 8 + 2 * t4;
                if (j0 > rqA)     s[nt][0] = -1e30f;
                if (j0 + 1 > rqA) s[nt][1] = -1e30f;
                if (j0 > rqB)     s[nt][2] = -1e30f;
                if (j0 + 1 > rqB) s[nt][3] = -1e30f;
            }
        }

        // ---- online softmax ----
        float mxA = -1e30f, mxB = -1e30f;
        #pragma unroll
        for (int nt = 0; nt < 8; nt++) {
            mxA = fmaxf(mxA, fmaxf(s[nt][0], s[nt][1]));
            mxB = fmaxf(mxB, fmaxf(s[nt][2], s[nt][3]));
        }
        #pragma unroll
        for (int off = 1; off < 4; off <<= 1) {
            mxA = fmaxf(mxA, __shfl_xor_sync(0xffffffffu, mxA, off));
            mxB = fmaxf(mxB, __shfl_xor_sync(0xffffffffu, mxB, off));
        }
        float mnA = fmaxf(mA, mxA), mnB = fmaxf(mB, mxB);
        float sclA = __expf(mA - mnA), sclB = __expf(mB - mnB);
        mA = mnA; mB = mnB;

        float lsA = 0.f, lsB = 0.f;
        #pragma unroll
        for (int nt = 0; nt < 8; nt++) {
            float p0 = __expf(s[nt][0] - mnA);
            float p1 = __expf(s[nt][1] - mnA);
            float p2 = __expf(s[nt][2] - mnB);
            float p3 = __expf(s[nt][3] - mnB);
            lsA += p0 + p1; lsB += p2 + p3;
            int j0 = nt * 8 + 2 * t4;
            Ps[rqA * KSTR + j0]     = ftf32(p0);
            Ps[rqA * KSTR + j0 + 1] = ftf32(p1);
            Ps[rqB * KSTR + j0]     = ftf32(p2);
            Ps[rqB * KSTR + j0 + 1] = ftf32(p3);
        }
        #pragma unroll
        for (int off = 1; off < 4; off <<= 1) {
            lsA += __shfl_xor_sync(0xffffffffu, lsA, off);
            lsB += __shfl_xor_sync(0xffffffffu, lsB, off);
        }
        lA = lA * sclA + lsA;
        lB = lB * sclB + lsB;
        #pragma unroll
        for (int nt = 0; nt < 8; nt++) {
            o[nt][0] *= sclA; o[nt][1] *= sclA;
            o[nt][2] *= sclB; o[nt][3] *= sclB;
        }
        __syncwarp();   // warp-local P strip visible

        // ---- O += P V ----
        #pragma unroll
        for (int ks = 0; ks < 8; ks++) {
            int k0 = ks * 8 + t4;
            uint32_t pf[4];
            pf[0] = __float_as_uint(Ps[rqA * KSTR + k0]);
            pf[1] = __float_as_uint(Ps[rqB * KSTR + k0]);
            pf[2] = __float_as_uint(Ps[rqA * KSTR + k0 + 4]);
            pf[3] = __float_as_uint(Ps[rqB * KSTR + k0 + 4]);
            #pragma unroll
            for (int nt = 0; nt < 8; nt++) {
                uint32_t vf[2];
                int dsw = (nt * 8 + g) ^ (t4 * 8);
                vf[0] = __float_as_uint(Vb[k0 * VSTR + dsw]);
                vf[1] = __float_as_uint(Vb[(k0 + 4) * VSTR + dsw]);
                mma8(o[nt], pf, vf, o[nt]);
            }
        }
    }

    // ---- normalize + write (tf32-rounded for proj DMA) ----
    float invA = 1.f / lA, invB = 1.f / lB;
    int nA = qt * 128 + rqA, nB = qt * 128 + rqB;
    #pragma unroll
    for (int nt = 0; nt < 8; nt++) {
        int c = h * HD + nt * 8 + 2 * t4;
        *(float2*)(g_attn + (size_t)nA * CDIM + c) =
            make_float2(ftf32(o[nt][0] * invA), ftf32(o[nt][1] * invA));
        *(float2*)(g_attn + (size_t)nB * CDIM + c) =
            make_float2(ftf32(o[nt][2] * invB), ftf32(o[nt][3] * invB));
    }
}

// ---------------------------------------------------------------------------

extern "C" void kernel_launch(void* const* d_in, const int* in_sizes, int n_in,
                              void* d_out, int out_size) {
    const float* x      = (const float*)d_in[0];  // [4096, 1024]
    const float* w_qkv  = (const float*)d_in[1];  // [3072, 1024]
    const float* w_proj = (const float*)d_in[2];  // [1024, 1024]
    const float* b_proj = (const float*)d_in[3];  // [1024]
    float* out = (float*)d_out;                   // [4096, 1024]

    (void)in_sizes; (void)n_in; (void)out_size;

    const int GEMM_SMEM = 4 * 128 * GPAD * 4;                                // 73728 B
    const int ATTN_SMEM = (2 * 64 * KSTR + 2 * 64 * VSTR + 128 * KSTR) * 4;  // 104448 B
    cudaFuncSetAttribute(tc_gemm<0>, cudaFuncAttributeMaxDynamicSharedMemorySize, GEMM_SMEM);
    cudaFuncSetAttribute(tc_gemm<1>, cudaFuncAttributeMaxDynamicSharedMemorySize, GEMM_SMEM);
    cudaFuncSetAttribute(attn_kernel, cudaFuncAttributeMaxDynamicSharedMemorySize, ATTN_SMEM);

    const size_t NPREP = ((size_t)NTOK * CDIM + 3 * CDIM * CDIM + CDIM * CDIM) / 4;
    prep_kernel<<<(unsigned)((NPREP + 255) / 256), 256>>>(x, w_qkv, w_proj);

    dim3 g1(3 * CDIM / 128, NTOK / 128);   // 24 x 32
    tc_gemm<0><<<g1, 256, GEMM_SMEM>>>(nullptr, nullptr);

    dim3 g2(NTOK / 128, HEADS);            // 32 x 16
    attn_kernel<<<g2, 256, ATTN_SMEM>>>();

    dim3 g3(CDIM / 128, NTOK / 128);       // 8 x 32
    tc_gemm<1><<<g3, 256, GEMM_SMEM>>>(b_proj, out);
}